// round 1
// baseline (speedup 1.0000x reference)
#include <cuda_runtime.h>
#include <cuda_bf16.h>
#include <math.h>

// ---------------------------------------------------------------------------
// CrossAttention with LoRA — fp32 baseline
// B=8, T=1024, S=256, C=1024, H=16, D=64, R=16, SCALING=1/16
// ---------------------------------------------------------------------------

#define Bsz   8
#define Tlen  1024
#define Slen  256
#define Cdim  1024
#define Hn    16
#define Dh    64
#define Rr    16

// scratch (device globals — no allocation allowed)
__device__ float g_Q [Bsz * Tlen * Cdim];          // 8192 x 1024
__device__ float g_KV[Bsz * Slen * 2 * Cdim];      // 2048 x 2048
__device__ float g_att[(long long)Bsz * Hn * Tlen * Slen]; // 128 x 1024 x 256
__device__ float g_Y [Bsz * Tlen * Cdim];          // 8192 x 1024
__device__ float g_tq[Bsz * Tlen * Rr];
__device__ float g_tf[Bsz * Slen * Rr];
__device__ float g_tp[Bsz * Tlen * Rr];

// ---------------------------------------------------------------------------
// Generic tiled SGEMM:  C[m,n] = sum_k A[m,k] * B'[k,n]  (+ bias + LoRA)
//   BT=true : B stored (N,K) row-major  -> B'[k,n] = B[n*ldb + k]
//   BT=false: B stored (K,N) row-major  -> B'[k,n] = B[k*ldb + n]
// Batched via blockIdx.z: offsets = z1*s?1 + z2*s?2 with z1=z/zdiv, z2=z%zdiv.
// Requires M%128==0, N%BN==0, K%16==0 (true for every call here).
// ---------------------------------------------------------------------------
template<int BN, int TN, bool BT>
__global__ void __launch_bounds__(256)
sgemm_kernel(const float* __restrict__ A, const float* __restrict__ B,
             float* __restrict__ C,
             int M, int N, int K, int lda, int ldb, int ldc,
             int zdiv,
             long long sA1, long long sA2,
             long long sB1, long long sB2,
             long long sC1, long long sC2,
             const float* __restrict__ bias,
             const float* __restrict__ lt,   // (M,16) or null
             const float* __restrict__ lb,   // (N,16) or null
             float scaling)
{
    constexpr int BM = 128;
    constexpr int BK = 16;

    __shared__ float As[BK][BM + 4];
    __shared__ float Bs[BK][BN + 4];
    __shared__ float lts[BM * 16];
    __shared__ float lbs[BN * 16];

    const int tid = threadIdx.x;
    const int z   = blockIdx.z;
    const int z1  = z / zdiv;
    const int z2  = z % zdiv;
    A += z1 * sA1 + z2 * sA2;
    B += z1 * sB1 + z2 * sB2;
    C += z1 * sC1 + z2 * sC2;

    const int bm = blockIdx.y * BM;
    const int bn = blockIdx.x * BN;

    const int ty = tid >> 4;   // 0..15 -> rows  ty*8 .. ty*8+7
    const int tx = tid & 15;   // 0..15 -> cols  tx*TN .. tx*TN+TN-1

    float acc[8][TN];
#pragma unroll
    for (int i = 0; i < 8; i++)
#pragma unroll
        for (int j = 0; j < TN; j++) acc[i][j] = 0.0f;

    const int numA4 = BM * BK / 4;   // 512
    const int numB4 = BN * BK / 4;

    for (int kt = 0; kt < K; kt += BK) {
        // --- load A tile (BM x BK), store transposed As[k][m]
#pragma unroll
        for (int i = tid; i < numA4; i += 256) {
            int row = i >> 2;       // BK/4 = 4 float4 per row
            int c4  = i & 3;
            float4 v = *reinterpret_cast<const float4*>(
                &A[(long long)(bm + row) * lda + kt + c4 * 4]);
            As[c4 * 4 + 0][row] = v.x;
            As[c4 * 4 + 1][row] = v.y;
            As[c4 * 4 + 2][row] = v.z;
            As[c4 * 4 + 3][row] = v.w;
        }
        // --- load B tile
        if (BT) {
#pragma unroll
            for (int i = tid; i < numB4; i += 256) {
                int row = i >> 2;
                int c4  = i & 3;
                float4 v = *reinterpret_cast<const float4*>(
                    &B[(long long)(bn + row) * ldb + kt + c4 * 4]);
                Bs[c4 * 4 + 0][row] = v.x;
                Bs[c4 * 4 + 1][row] = v.y;
                Bs[c4 * 4 + 2][row] = v.z;
                Bs[c4 * 4 + 3][row] = v.w;
            }
        } else {
#pragma unroll
            for (int i = tid; i < numB4; i += 256) {
                int row = i / (BN / 4);
                int c4  = i % (BN / 4);
                float4 v = *reinterpret_cast<const float4*>(
                    &B[(long long)(kt + row) * ldb + bn + c4 * 4]);
                *reinterpret_cast<float4*>(&Bs[row][c4 * 4]) = v;
            }
        }
        __syncthreads();

#pragma unroll
        for (int k = 0; k < BK; k++) {
            float af[8], bfr[TN];
#pragma unroll
            for (int i = 0; i < 8; i += 4) {
                float4 v = *reinterpret_cast<const float4*>(&As[k][ty * 8 + i]);
                af[i] = v.x; af[i+1] = v.y; af[i+2] = v.z; af[i+3] = v.w;
            }
#pragma unroll
            for (int j = 0; j < TN; j += 4) {
                float4 v = *reinterpret_cast<const float4*>(&Bs[k][tx * TN + j]);
                bfr[j] = v.x; bfr[j+1] = v.y; bfr[j+2] = v.z; bfr[j+3] = v.w;
            }
#pragma unroll
            for (int i = 0; i < 8; i++)
#pragma unroll
                for (int j = 0; j < TN; j++)
                    acc[i][j] = fmaf(af[i], bfr[j], acc[i][j]);
        }
        __syncthreads();
    }

    // --- epilogue: LoRA tiles to smem
    if (lt != nullptr) {
        for (int i = tid; i < BM * 16; i += 256) lts[i] = lt[(long long)bm * 16 + i];
        for (int i = tid; i < BN * 16; i += 256) lbs[i] = lb[(long long)bn * 16 + i];
        __syncthreads();
    }

#pragma unroll
    for (int i = 0; i < 8; i++) {
        const int row = bm + ty * 8 + i;
        float outv[TN];
#pragma unroll
        for (int j = 0; j < TN; j++) {
            float v = acc[i][j];
            const int col = bn + tx * TN + j;
            if (bias) v += bias[col];
            if (lt) {
                float s = 0.0f;
#pragma unroll
                for (int r = 0; r < 16; r++)
                    s = fmaf(lts[(ty * 8 + i) * 16 + r], lbs[(tx * TN + j) * 16 + r], s);
                v = fmaf(scaling, s, v);
            }
            outv[j] = v;
        }
#pragma unroll
        for (int j = 0; j < TN; j += 4) {
            float4 v4 = make_float4(outv[j], outv[j+1], outv[j+2], outv[j+3]);
            *reinterpret_cast<float4*>(&C[(long long)row * ldc + bn + tx * TN + j]) = v4;
        }
    }
}

// ---------------------------------------------------------------------------
// LoRA intermediate: T[m,r] = sum_k X[m,k] * Amat[r,k]   (K=1024, R=16)
// Block covers 64 rows; thread = (mg, r), 4 rows each.
// ---------------------------------------------------------------------------
__global__ void __launch_bounds__(256)
lora_t_kernel(const float* __restrict__ X, const float* __restrict__ Amat,
              float* __restrict__ T)
{
    __shared__ float xs[64][68];
    __shared__ float as_[16][65];

    const int tid = threadIdx.x;
    const int bm  = blockIdx.x * 64;
    const int r   = tid & 15;
    const int mg  = tid >> 4;   // 0..15

    float a0 = 0.f, a1 = 0.f, a2 = 0.f, a3 = 0.f;

    for (int kt = 0; kt < 1024; kt += 64) {
#pragma unroll
        for (int i = tid; i < 1024; i += 256) {
            int row = i >> 4, c4 = i & 15;
            float4 v = *reinterpret_cast<const float4*>(
                &X[(long long)(bm + row) * 1024 + kt + c4 * 4]);
            *reinterpret_cast<float4*>(&xs[row][c4 * 4]) = v;
        }
#pragma unroll
        for (int i = tid; i < 1024; i += 256) {
            int row = i >> 6, kk = i & 63;
            as_[row][kk] = Amat[row * 1024 + kt + kk];
        }
        __syncthreads();
#pragma unroll 16
        for (int kk = 0; kk < 64; kk++) {
            float a = as_[r][kk];
            a0 = fmaf(xs[mg * 4 + 0][kk], a, a0);
            a1 = fmaf(xs[mg * 4 + 1][kk], a, a1);
            a2 = fmaf(xs[mg * 4 + 2][kk], a, a2);
            a3 = fmaf(xs[mg * 4 + 3][kk], a, a3);
        }
        __syncthreads();
    }
    T[(long long)(bm + mg * 4 + 0) * 16 + r] = a0;
    T[(long long)(bm + mg * 4 + 1) * 16 + r] = a1;
    T[(long long)(bm + mg * 4 + 2) * 16 + r] = a2;
    T[(long long)(bm + mg * 4 + 3) * 16 + r] = a3;
}

// ---------------------------------------------------------------------------
// Masked softmax over att (BH=128, T=1024, S=256): scale 1/8, mask s<=t (tril)
// One warp per (bh, t) row.
// ---------------------------------------------------------------------------
__global__ void __launch_bounds__(256)
softmax_kernel(float* __restrict__ att)
{
    const int warp = threadIdx.x >> 5;
    const int lane = threadIdx.x & 31;
    const long long row = (long long)blockIdx.x * 8 + warp;
    const int t = (int)(row & 1023);
    float* p = att + row * 256;

    float v[8];
    float mx = -1e30f;
#pragma unroll
    for (int j = 0; j < 8; j++) {
        int s = j * 32 + lane;
        float x = p[s] * 0.125f;
        if (s > t) x = -1e30f;
        v[j] = x;
        mx = fmaxf(mx, x);
    }
#pragma unroll
    for (int o = 16; o > 0; o >>= 1) mx = fmaxf(mx, __shfl_xor_sync(0xffffffffu, mx, o));
    float sum = 0.0f;
#pragma unroll
    for (int j = 0; j < 8; j++) { v[j] = __expf(v[j] - mx); sum += v[j]; }
#pragma unroll
    for (int o = 16; o > 0; o >>= 1) sum += __shfl_xor_sync(0xffffffffu, sum, o);
    const float inv = 1.0f / sum;
#pragma unroll
    for (int j = 0; j < 8; j++) p[j * 32 + lane] = v[j] * inv;
}

// ---------------------------------------------------------------------------
// Launch
// ---------------------------------------------------------------------------
extern "C" void kernel_launch(void* const* d_in, const int* in_sizes, int n_in,
                              void* d_out, int out_size)
{
    const float* x  = (const float*)d_in[0];
    const float* ft = (const float*)d_in[1];
    const float* Wq = (const float*)d_in[2];
    const float* bq = (const float*)d_in[3];
    const float* Aq = (const float*)d_in[4];
    const float* Bq = (const float*)d_in[5];
    const float* Wf = (const float*)d_in[6];
    const float* bfv= (const float*)d_in[7];
    const float* Af = (const float*)d_in[8];
    const float* Bf = (const float*)d_in[9];
    const float* Wp = (const float*)d_in[10];
    const float* bp = (const float*)d_in[11];
    const float* Ap = (const float*)d_in[12];
    const float* Bp = (const float*)d_in[13];
    float* out = (float*)d_out;

    float *dQ, *dKV, *dAtt, *dY, *dtq, *dtf, *dtp;
    cudaGetSymbolAddress((void**)&dQ,   g_Q);
    cudaGetSymbolAddress((void**)&dKV,  g_KV);
    cudaGetSymbolAddress((void**)&dAtt, g_att);
    cudaGetSymbolAddress((void**)&dY,   g_Y);
    cudaGetSymbolAddress((void**)&dtq,  g_tq);
    cudaGetSymbolAddress((void**)&dtf,  g_tf);
    cudaGetSymbolAddress((void**)&dtp,  g_tp);

    const float SC = 1.0f / 16.0f;

    // 1) LoRA intermediates for q
    lora_t_kernel<<<128, 256>>>(x, Aq, dtq);

    // 2) Q = x @ Wq^T + bq + tq @ Bq^T * s      (8192 x 1024 x 1024)
    sgemm_kernel<128, 8, true><<<dim3(8, 64, 1), 256>>>(
        x, Wq, dQ, 8192, 1024, 1024, 1024, 1024, 1024,
        1, 0, 0, 0, 0, 0, 0, bq, dtq, Bq, SC);

    // 3) LoRA intermediates for kv
    lora_t_kernel<<<32, 256>>>(ft, Af, dtf);

    // 4) KV = feature @ Wf^T + bf + tf @ Bf^T * s   (2048 x 2048 x 1024)
    sgemm_kernel<128, 8, true><<<dim3(16, 16, 1), 256>>>(
        ft, Wf, dKV, 2048, 2048, 1024, 1024, 1024, 2048,
        1, 0, 0, 0, 0, 0, 0, bfv, dtf, Bf, SC);

    // 5) att = Q . K^T  batched over (b,h): M=1024(t), N=256(s), K=64(d)
    sgemm_kernel<128, 8, true><<<dim3(2, 8, 128), 256>>>(
        dQ, dKV, dAtt, 1024, 256, 64, 1024, 2048, 256,
        16,
        /*sA*/ 1024LL * 1024, 64,
        /*sB*/ 256LL * 2048, 64,
        /*sC*/ 16LL * 1024 * 256, 1024LL * 256,
        nullptr, nullptr, nullptr, 0.f);

    // 6) masked softmax
    softmax_kernel<<<16384, 256>>>(dAtt);

    // 7) y = att . V  batched: M=1024(t), N=64(d), K=256(s)
    sgemm_kernel<64, 4, false><<<dim3(1, 8, 128), 256>>>(
        dAtt, dKV + 1024, dY, 1024, 64, 256, 256, 2048, 1024,
        16,
        /*sA*/ 16LL * 1024 * 256, 1024LL * 256,
        /*sB*/ 256LL * 2048, 64,
        /*sC*/ 1024LL * 1024, 64,
        nullptr, nullptr, nullptr, 0.f);

    // 8) LoRA intermediates for proj
    lora_t_kernel<<<128, 256>>>(dY, Ap, dtp);

    // 9) out = y @ Wp^T + bp + tp @ Bp^T * s
    sgemm_kernel<128, 8, true><<<dim3(8, 64, 1), 256>>>(
        dY, Wp, out, 8192, 1024, 1024, 1024, 1024, 1024,
        1, 0, 0, 0, 0, 0, 0, bp, dtp, Bp, SC);
}

// round 3
// speedup vs baseline: 1.9751x; 1.9751x over previous
#include <cuda_runtime.h>
#include <cuda_bf16.h>
#include <math.h>
#include <stdint.h>

// ---------------------------------------------------------------------------
// CrossAttention with LoRA — round 3: mma.sync split-bf16 projections
// (tcgen05 unavailable: harness PTX targets compute_103 without 'a' features)
// B=8, T=1024, S=256, C=1024, H=16, D=64, R=16, SCALING=1/16
// ---------------------------------------------------------------------------

#define Bsz   8
#define Tlen  1024
#define Slen  256
#define Cdim  1024

// fp32 scratch
__device__ __align__(16) float g_Q [Bsz * Tlen * Cdim];
__device__ __align__(16) float g_KV[Bsz * Slen * 2 * Cdim];
__device__ __align__(16) float g_att[(long long)Bsz * 16 * Tlen * Slen];
__device__ __align__(16) float g_Y [Bsz * Tlen * Cdim];

// bf16 hi/lo splits of activations + weights
__device__ __align__(16) __nv_bfloat16 g_xhi[Bsz*Tlen*Cdim], g_xlo[Bsz*Tlen*Cdim];
__device__ __align__(16) __nv_bfloat16 g_fhi[Bsz*Slen*Cdim], g_flo[Bsz*Slen*Cdim];
__device__ __align__(16) __nv_bfloat16 g_yhi[Bsz*Tlen*Cdim], g_ylo[Bsz*Tlen*Cdim];
__device__ __align__(16) __nv_bfloat16 g_wqhi[Cdim*Cdim],   g_wqlo[Cdim*Cdim];
__device__ __align__(16) __nv_bfloat16 g_wfhi[2*Cdim*Cdim], g_wflo[2*Cdim*Cdim];
__device__ __align__(16) __nv_bfloat16 g_wphi[Cdim*Cdim],   g_wplo[Cdim*Cdim];

// LoRA factors in split bf16, K-padded to 32 (cols 16..31 zero)
__device__ __align__(16) __nv_bfloat16 g_tqh[Bsz*Tlen*32], g_tql[Bsz*Tlen*32];
__device__ __align__(16) __nv_bfloat16 g_tfh[Bsz*Slen*32], g_tfl[Bsz*Slen*32];
__device__ __align__(16) __nv_bfloat16 g_tph[Bsz*Tlen*32], g_tpl[Bsz*Tlen*32];
__device__ __align__(16) __nv_bfloat16 g_bqh[Cdim*32],   g_bql[Cdim*32];
__device__ __align__(16) __nv_bfloat16 g_bfh[2*Cdim*32], g_bfl[2*Cdim*32];
__device__ __align__(16) __nv_bfloat16 g_bph[Cdim*32],   g_bpl[Cdim*32];

// ---------------------------------------------------------------------------
// helpers
// ---------------------------------------------------------------------------
__device__ __forceinline__ uint32_t smem_u32(const void* p) {
    uint32_t a;
    asm("{ .reg .u64 t; cvta.to.shared.u64 t, %1; cvt.u32.u64 %0, t; }" : "=r"(a) : "l"(p));
    return a;
}
__device__ __forceinline__ void cp16(uint32_t dst, const void* src) {
    asm volatile("cp.async.cg.shared.global [%0], [%1], 16;" :: "r"(dst), "l"(src));
}
__device__ __forceinline__ void cp_commit() {
    asm volatile("cp.async.commit_group;" ::: "memory");
}
__device__ __forceinline__ void ldm_x4(uint32_t& r0, uint32_t& r1, uint32_t& r2, uint32_t& r3,
                                       uint32_t addr) {
    asm volatile("ldmatrix.sync.aligned.m8n8.x4.shared.b16 {%0,%1,%2,%3}, [%4];"
                 : "=r"(r0), "=r"(r1), "=r"(r2), "=r"(r3) : "r"(addr));
}
__device__ __forceinline__ void mma_bf16(float* c, const uint32_t* a, const uint32_t* b) {
    asm volatile(
        "mma.sync.aligned.m16n8k16.row.col.f32.bf16.bf16.f32 "
        "{%0,%1,%2,%3}, {%4,%5,%6,%7}, {%8,%9}, {%0,%1,%2,%3};"
        : "+f"(c[0]), "+f"(c[1]), "+f"(c[2]), "+f"(c[3])
        : "r"(a[0]), "r"(a[1]), "r"(a[2]), "r"(a[3]), "r"(b[0]), "r"(b[1]));
}

// ---------------------------------------------------------------------------
// fp32 -> (hi, lo) bf16 split
// ---------------------------------------------------------------------------
__global__ void __launch_bounds__(256)
split_kernel(const float4* __restrict__ in, __nv_bfloat162* __restrict__ hi,
             __nv_bfloat162* __restrict__ lo, int n4)
{
    int i = blockIdx.x * 256 + threadIdx.x;
    if (i >= n4) return;
    float4 v = in[i];
    __nv_bfloat16 h0 = __float2bfloat16(v.x);
    __nv_bfloat16 h1 = __float2bfloat16(v.y);
    __nv_bfloat16 h2 = __float2bfloat16(v.z);
    __nv_bfloat16 h3 = __float2bfloat16(v.w);
    __nv_bfloat16 l0 = __float2bfloat16(v.x - __bfloat162float(h0));
    __nv_bfloat16 l1 = __float2bfloat16(v.y - __bfloat162float(h1));
    __nv_bfloat16 l2 = __float2bfloat16(v.z - __bfloat162float(h2));
    __nv_bfloat16 l3 = __float2bfloat16(v.w - __bfloat162float(h3));
    hi[2*i]   = __nv_bfloat162(h0, h1);
    hi[2*i+1] = __nv_bfloat162(h2, h3);
    lo[2*i]   = __nv_bfloat162(l0, l1);
    lo[2*i+1] = __nv_bfloat162(l2, l3);
}

// split a (rows x 16) fp32 matrix into (rows x 32) hi/lo bf16, cols 16..31 = 0
__global__ void __launch_bounds__(256)
splitpad_kernel(const float* __restrict__ B, __nv_bfloat16* __restrict__ hi,
                __nv_bfloat16* __restrict__ lo, int rows)
{
    int row = blockIdx.x * 256 + threadIdx.x;
    if (row >= rows) return;
#pragma unroll
    for (int j = 0; j < 16; j++) {
        float v = B[row * 16 + j];
        __nv_bfloat16 h = __float2bfloat16(v);
        __nv_bfloat16 l = __float2bfloat16(v - __bfloat162float(h));
        hi[row * 32 + j] = h;
        lo[row * 32 + j] = l;
        hi[row * 32 + 16 + j] = __float2bfloat16(0.0f);
        lo[row * 32 + 16 + j] = __float2bfloat16(0.0f);
    }
}

// ---------------------------------------------------------------------------
// LoRA intermediate: T[m,r] = scale * sum_k X[m,k] * Amat[r,k], emitted as
// split bf16 padded to 32 cols (16..31 zero).
// ---------------------------------------------------------------------------
__global__ void __launch_bounds__(256)
lora_t_kernel(const float* __restrict__ X, const float* __restrict__ Amat,
              __nv_bfloat16* __restrict__ Thi, __nv_bfloat16* __restrict__ Tlo,
              float scale)
{
    __shared__ float xs[64][68];
    __shared__ float as_[16][65];

    const int tid = threadIdx.x;
    const int bm  = blockIdx.x * 64;
    const int r   = tid & 15;
    const int mg  = tid >> 4;

    float a0 = 0.f, a1 = 0.f, a2 = 0.f, a3 = 0.f;

    for (int kt = 0; kt < 1024; kt += 64) {
#pragma unroll
        for (int i = tid; i < 1024; i += 256) {
            int row = i >> 4, c4 = i & 15;
            float4 v = *reinterpret_cast<const float4*>(
                &X[(long long)(bm + row) * 1024 + kt + c4 * 4]);
            *reinterpret_cast<float4*>(&xs[row][c4 * 4]) = v;
        }
#pragma unroll
        for (int i = tid; i < 1024; i += 256) {
            int row = i >> 6, kk = i & 63;
            as_[row][kk] = Amat[row * 1024 + kt + kk];
        }
        __syncthreads();
#pragma unroll 16
        for (int kk = 0; kk < 64; kk++) {
            float a = as_[r][kk];
            a0 = fmaf(xs[mg * 4 + 0][kk], a, a0);
            a1 = fmaf(xs[mg * 4 + 1][kk], a, a1);
            a2 = fmaf(xs[mg * 4 + 2][kk], a, a2);
            a3 = fmaf(xs[mg * 4 + 3][kk], a, a3);
        }
        __syncthreads();
    }
    const __nv_bfloat16 z = __float2bfloat16(0.0f);
#pragma unroll
    for (int q = 0; q < 4; q++) {
        float v = (q == 0 ? a0 : q == 1 ? a1 : q == 2 ? a2 : a3) * scale;
        long long row = bm + mg * 4 + q;
        __nv_bfloat16 h = __float2bfloat16(v);
        __nv_bfloat16 l = __float2bfloat16(v - __bfloat162float(h));
        Thi[row * 32 + r] = h;       Tlo[row * 32 + r] = l;
        Thi[row * 32 + 16 + r] = z;  Tlo[row * 32 + 16 + r] = z;
    }
}

// ---------------------------------------------------------------------------
// split-bf16 mma.sync GEMM:
//   C[m,n] = sum_k A[m,k]*B[n,k] + bias[n] + sum_r LT[m,r]*LB[n,r]
// A:(M,K) hi/lo bf16 row-major; B:(N,K) hi/lo bf16 row-major; K % 32 == 0.
// LT:(M,32) LB:(N,32) split bf16 (zero-padded, LT pre-scaled).
// CTA tile 128x128, BK=32, cp.async double buffer. grid = (N/128, M/128).
// ---------------------------------------------------------------------------
#define MG_STAGE 32768   // 4 tiles x 128 x 32 x 2B
#define MG_SMEM  (2 * MG_STAGE)

__global__ void __launch_bounds__(256)
mma_gemm(const __nv_bfloat16* __restrict__ Ahi, const __nv_bfloat16* __restrict__ Alo,
         const __nv_bfloat16* __restrict__ Bhi, const __nv_bfloat16* __restrict__ Blo,
         const __nv_bfloat16* __restrict__ LThi, const __nv_bfloat16* __restrict__ LTlo,
         const __nv_bfloat16* __restrict__ LBhi, const __nv_bfloat16* __restrict__ LBlo,
         float* __restrict__ C, int K, int N, const float* __restrict__ bias)
{
    extern __shared__ char smem[];
    const uint32_t sb = smem_u32(smem);
    const int tid  = threadIdx.x;
    const int lane = tid & 31;
    const int warp = tid >> 5;
    const int wm   = warp >> 1;          // 0..3  (32-row slice)
    const int wn   = warp & 1;           // 0..1  (64-col slice)
    const int bm = blockIdx.y * 128;
    const int bn = blockIdx.x * 128;

    const int KCH = K >> 5;              // 32-wide chunks of the main GEMM
    const int NC  = KCH + 1;             // + 1 LoRA chunk

    float acc[2][8][4];
#pragma unroll
    for (int m = 0; m < 2; m++)
#pragma unroll
        for (int n = 0; n < 8; n++)
#pragma unroll
            for (int j = 0; j < 4; j++) acc[m][n][j] = 0.0f;

    // ---- chunk loader (cp.async), tiles: 0=Ahi 1=Alo 2=Bhi 3=Blo ----
    auto load_chunk = [&](int ch, int st) {
        const bool lora = (ch == KCH);
        const int kt = ch << 5;
#pragma unroll
        for (int i = tid; i < 2048; i += 256) {
            int tile = i >> 9;
            int idx  = i & 511;
            int row  = idx >> 2;
            int c4   = idx & 3;
            const __nv_bfloat16* g;
            long long off;
            if (!lora) {
                g = (tile == 0) ? Ahi : (tile == 1) ? Alo : (tile == 2) ? Bhi : Blo;
                int r0 = (tile < 2) ? bm : bn;
                off = (long long)(r0 + row) * K + kt + c4 * 8;
            } else {
                g = (tile == 0) ? LThi : (tile == 1) ? LTlo : (tile == 2) ? LBhi : LBlo;
                int r0 = (tile < 2) ? bm : bn;
                off = (long long)(r0 + row) * 32 + c4 * 8;
            }
            uint32_t dst = sb + st * MG_STAGE + tile * 8192 + row * 64
                         + ((c4 ^ ((row >> 1) & 3)) << 4);
            cp16(dst, g + off);
        }
        cp_commit();
    };

    load_chunk(0, 0);

    for (int ch = 0; ch < NC; ch++) {
        const int st = ch & 1;
        if (ch + 1 < NC) {
            load_chunk(ch + 1, st ^ 1);
            asm volatile("cp.async.wait_group 1;" ::: "memory");
        } else {
            asm volatile("cp.async.wait_group 0;" ::: "memory");
        }
        __syncthreads();

        const uint32_t stb = sb + st * MG_STAGE;
#pragma unroll
        for (int kk = 0; kk < 2; kk++) {
            uint32_t ah[2][4], al[2][4];
#pragma unroll
            for (int mf = 0; mf < 2; mf++) {
                int row = wm * 32 + mf * 16 + (lane & 15);
                int c4  = kk * 2 + (lane >> 4);
                uint32_t sw = (uint32_t)((c4 ^ ((row >> 1) & 3)) << 4);
                uint32_t ad = stb + row * 64 + sw;
                ldm_x4(ah[mf][0], ah[mf][1], ah[mf][2], ah[mf][3], ad);
                ldm_x4(al[mf][0], al[mf][1], al[mf][2], al[mf][3], ad + 8192);
            }
            uint32_t bh[8][2], bl[8][2];
#pragma unroll
            for (int p = 0; p < 4; p++) {
                int row = wn * 64 + p * 16 + (lane & 15);
                int c4  = kk * 2 + (lane >> 4);
                uint32_t sw = (uint32_t)((c4 ^ ((row >> 1) & 3)) << 4);
                uint32_t ad = stb + 16384 + row * 64 + sw;
                uint32_t r0, r1, r2, r3;
                ldm_x4(r0, r1, r2, r3, ad);
                bh[2*p][0] = r0; bh[2*p][1] = r2;
                bh[2*p+1][0] = r1; bh[2*p+1][1] = r3;
                ldm_x4(r0, r1, r2, r3, ad + 8192);
                bl[2*p][0] = r0; bl[2*p][1] = r2;
                bl[2*p+1][0] = r1; bl[2*p+1][1] = r3;
            }
#pragma unroll
            for (int mf = 0; mf < 2; mf++)
#pragma unroll
                for (int n = 0; n < 8; n++) {
                    mma_bf16(acc[mf][n], ah[mf], bh[n]);
                    mma_bf16(acc[mf][n], ah[mf], bl[n]);
                    mma_bf16(acc[mf][n], al[mf], bh[n]);
                }
        }
        __syncthreads();
    }

    // ---- epilogue: bias + store ----
#pragma unroll
    for (int mf = 0; mf < 2; mf++) {
        int r1 = bm + wm * 32 + mf * 16 + (lane >> 2);
#pragma unroll
        for (int n = 0; n < 8; n++) {
            int col = bn + wn * 64 + n * 8 + (lane & 3) * 2;
            float b0 = bias[col], b1 = bias[col + 1];
            float2 v0 = make_float2(acc[mf][n][0] + b0, acc[mf][n][1] + b1);
            float2 v1 = make_float2(acc[mf][n][2] + b0, acc[mf][n][3] + b1);
            *reinterpret_cast<float2*>(&C[(long long)r1 * N + col]) = v0;
            *reinterpret_cast<float2*>(&C[(long long)(r1 + 8) * N + col]) = v1;
        }
    }
}

// ---------------------------------------------------------------------------
// fp32 SIMT GEMM (attention QK / AV)
// ---------------------------------------------------------------------------
template<int BN, int TN, bool BT>
__global__ void __launch_bounds__(256)
sgemm_kernel(const float* __restrict__ A, const float* __restrict__ B,
             float* __restrict__ C,
             int M, int N, int K, int lda, int ldb, int ldc,
             int zdiv,
             long long sA1, long long sA2,
             long long sB1, long long sB2,
             long long sC1, long long sC2)
{
    constexpr int BM = 128;
    constexpr int BK = 16;

    __shared__ float As[BK][BM + 4];
    __shared__ float Bs[BK][BN + 4];

    const int tid = threadIdx.x;
    const int z   = blockIdx.z;
    const int z1  = z / zdiv;
    const int z2  = z % zdiv;
    A += z1 * sA1 + z2 * sA2;
    B += z1 * sB1 + z2 * sB2;
    C += z1 * sC1 + z2 * sC2;

    const int bm = blockIdx.y * BM;
    const int bn = blockIdx.x * BN;
    const int ty = tid >> 4;
    const int tx = tid & 15;

    float acc[8][TN];
#pragma unroll
    for (int i = 0; i < 8; i++)
#pragma unroll
        for (int j = 0; j < TN; j++) acc[i][j] = 0.0f;

    const int numA4 = BM * BK / 4;
    const int numB4 = BN * BK / 4;

    for (int kt = 0; kt < K; kt += BK) {
#pragma unroll
        for (int i = tid; i < numA4; i += 256) {
            int row = i >> 2;
            int c4  = i & 3;
            float4 v = *reinterpret_cast<const float4*>(
                &A[(long long)(bm + row) * lda + kt + c4 * 4]);
            As[c4 * 4 + 0][row] = v.x;
            As[c4 * 4 + 1][row] = v.y;
            As[c4 * 4 + 2][row] = v.z;
            As[c4 * 4 + 3][row] = v.w;
        }
        if (BT) {
#pragma unroll
            for (int i = tid; i < numB4; i += 256) {
                int row = i >> 2;
                int c4  = i & 3;
                float4 v = *reinterpret_cast<const float4*>(
                    &B[(long long)(bn + row) * ldb + kt + c4 * 4]);
                Bs[c4 * 4 + 0][row] = v.x;
                Bs[c4 * 4 + 1][row] = v.y;
                Bs[c4 * 4 + 2][row] = v.z;
                Bs[c4 * 4 + 3][row] = v.w;
            }
        } else {
#pragma unroll
            for (int i = tid; i < numB4; i += 256) {
                int row = i / (BN / 4);
                int c4  = i % (BN / 4);
                float4 v = *reinterpret_cast<const float4*>(
                    &B[(long long)(kt + row) * ldb + bn + c4 * 4]);
                *reinterpret_cast<float4*>(&Bs[row][c4 * 4]) = v;
            }
        }
        __syncthreads();

#pragma unroll
        for (int k = 0; k < BK; k++) {
            float af[8], bfr[TN];
#pragma unroll
            for (int i = 0; i < 8; i += 4) {
                float4 v = *reinterpret_cast<const float4*>(&As[k][ty * 8 + i]);
                af[i] = v.x; af[i+1] = v.y; af[i+2] = v.z; af[i+3] = v.w;
            }
#pragma unroll
            for (int j = 0; j < TN; j += 4) {
                float4 v = *reinterpret_cast<const float4*>(&Bs[k][tx * TN + j]);
                bfr[j] = v.x; bfr[j+1] = v.y; bfr[j+2] = v.z; bfr[j+3] = v.w;
            }
#pragma unroll
            for (int i = 0; i < 8; i++)
#pragma unroll
                for (int j = 0; j < TN; j++)
                    acc[i][j] = fmaf(af[i], bfr[j], acc[i][j]);
        }
        __syncthreads();
    }

#pragma unroll
    for (int i = 0; i < 8; i++) {
        const int row = bm + ty * 8 + i;
#pragma unroll
        for (int j = 0; j < TN; j += 4) {
            float4 v4 = make_float4(acc[i][j], acc[i][j+1], acc[i][j+2], acc[i][j+3]);
            *reinterpret_cast<float4*>(&C[(long long)row * ldc + bn + tx * TN + j]) = v4;
        }
    }
}

// ---------------------------------------------------------------------------
// Masked softmax
// ---------------------------------------------------------------------------
__global__ void __launch_bounds__(256)
softmax_kernel(float* __restrict__ att)
{
    const int warp = threadIdx.x >> 5;
    const int lane = threadIdx.x & 31;
    const long long row = (long long)blockIdx.x * 8 + warp;
    const int t = (int)(row & 1023);
    float* p = att + row * 256;

    float v[8];
    float mx = -1e30f;
#pragma unroll
    for (int j = 0; j < 8; j++) {
        int s = j * 32 + lane;
        float x = p[s] * 0.125f;
        if (s > t) x = -1e30f;
        v[j] = x;
        mx = fmaxf(mx, x);
    }
#pragma unroll
    for (int o = 16; o > 0; o >>= 1) mx = fmaxf(mx, __shfl_xor_sync(0xffffffffu, mx, o));
    float sum = 0.0f;
#pragma unroll
    for (int j = 0; j < 8; j++) { v[j] = __expf(v[j] - mx); sum += v[j]; }
#pragma unroll
    for (int o = 16; o > 0; o >>= 1) sum += __shfl_xor_sync(0xffffffffu, sum, o);
    const float inv = 1.0f / sum;
#pragma unroll
    for (int j = 0; j < 8; j++) p[j * 32 + lane] = v[j] * inv;
}

// ---------------------------------------------------------------------------
// Launch
// ---------------------------------------------------------------------------
extern "C" void kernel_launch(void* const* d_in, const int* in_sizes, int n_in,
                              void* d_out, int out_size)
{
    const float* x  = (const float*)d_in[0];
    const float* ft = (const float*)d_in[1];
    const float* Wq = (const float*)d_in[2];
    const float* bq = (const float*)d_in[3];
    const float* Aq = (const float*)d_in[4];
    const float* Bq = (const float*)d_in[5];
    const float* Wf = (const float*)d_in[6];
    const float* bfv= (const float*)d_in[7];
    const float* Af = (const float*)d_in[8];
    const float* Bf = (const float*)d_in[9];
    const float* Wp = (const float*)d_in[10];
    const float* bp = (const float*)d_in[11];
    const float* Ap = (const float*)d_in[12];
    const float* Bp = (const float*)d_in[13];
    float* out = (float*)d_out;

    float *dQ, *dKV, *dAtt, *dY;
    cudaGetSymbolAddress((void**)&dQ,   g_Q);
    cudaGetSymbolAddress((void**)&dKV,  g_KV);
    cudaGetSymbolAddress((void**)&dAtt, g_att);
    cudaGetSymbolAddress((void**)&dY,   g_Y);

    __nv_bfloat16 *xhi, *xlo, *fhi, *flo, *yhi, *ylo;
    __nv_bfloat16 *wqhi, *wqlo, *wfhi, *wflo, *wphi, *wplo;
    __nv_bfloat16 *tqh, *tql, *tfh, *tfl, *tph, *tpl;
    __nv_bfloat16 *bqh, *bql, *bfh, *bfl, *bph, *bpl;
    cudaGetSymbolAddress((void**)&xhi, g_xhi);  cudaGetSymbolAddress((void**)&xlo, g_xlo);
    cudaGetSymbolAddress((void**)&fhi, g_fhi);  cudaGetSymbolAddress((void**)&flo, g_flo);
    cudaGetSymbolAddress((void**)&yhi, g_yhi);  cudaGetSymbolAddress((void**)&ylo, g_ylo);
    cudaGetSymbolAddress((void**)&wqhi, g_wqhi); cudaGetSymbolAddress((void**)&wqlo, g_wqlo);
    cudaGetSymbolAddress((void**)&wfhi, g_wfhi); cudaGetSymbolAddress((void**)&wflo, g_wflo);
    cudaGetSymbolAddress((void**)&wphi, g_wphi); cudaGetSymbolAddress((void**)&wplo, g_wplo);
    cudaGetSymbolAddress((void**)&tqh, g_tqh);  cudaGetSymbolAddress((void**)&tql, g_tql);
    cudaGetSymbolAddress((void**)&tfh, g_tfh);  cudaGetSymbolAddress((void**)&tfl, g_tfl);
    cudaGetSymbolAddress((void**)&tph, g_tph);  cudaGetSymbolAddress((void**)&tpl, g_tpl);
    cudaGetSymbolAddress((void**)&bqh, g_bqh);  cudaGetSymbolAddress((void**)&bql, g_bql);
    cudaGetSymbolAddress((void**)&bfh, g_bfh);  cudaGetSymbolAddress((void**)&bfl, g_bfl);
    cudaGetSymbolAddress((void**)&bph, g_bph);  cudaGetSymbolAddress((void**)&bpl, g_bpl);

    cudaFuncSetAttribute(mma_gemm, cudaFuncAttributeMaxDynamicSharedMemorySize, MG_SMEM);

    const float SC = 1.0f / 16.0f;

    // splits
    split_kernel<<<(Bsz*Tlen*Cdim/4 + 255)/256, 256>>>((const float4*)x,  (__nv_bfloat162*)xhi,  (__nv_bfloat162*)xlo,  Bsz*Tlen*Cdim/4);
    split_kernel<<<(Cdim*Cdim/4 + 255)/256, 256>>>((const float4*)Wq, (__nv_bfloat162*)wqhi, (__nv_bfloat162*)wqlo, Cdim*Cdim/4);
    split_kernel<<<(Bsz*Slen*Cdim/4 + 255)/256, 256>>>((const float4*)ft, (__nv_bfloat162*)fhi,  (__nv_bfloat162*)flo,  Bsz*Slen*Cdim/4);
    split_kernel<<<(2*Cdim*Cdim/4 + 255)/256, 256>>>((const float4*)Wf, (__nv_bfloat162*)wfhi, (__nv_bfloat162*)wflo, 2*Cdim*Cdim/4);
    split_kernel<<<(Cdim*Cdim/4 + 255)/256, 256>>>((const float4*)Wp, (__nv_bfloat162*)wphi, (__nv_bfloat162*)wplo, Cdim*Cdim/4);

    // LoRA factors (scaled, split, padded)
    lora_t_kernel<<<128, 256>>>(x, Aq, tqh, tql, SC);
    lora_t_kernel<<<32, 256>>>(ft, Af, tfh, tfl, SC);
    splitpad_kernel<<<(Cdim + 255)/256, 256>>>(Bq, bqh, bql, Cdim);
    splitpad_kernel<<<(2*Cdim + 255)/256, 256>>>(Bf, bfh, bfl, 2*Cdim);
    splitpad_kernel<<<(Cdim + 255)/256, 256>>>(Bp, bph, bpl, Cdim);

    // Q = x @ Wq^T + bq + lora   (8192 x 1024 x 1024)
    mma_gemm<<<dim3(8, 64), 256, MG_SMEM>>>(xhi, xlo, wqhi, wqlo,
                                            tqh, tql, bqh, bql, dQ, 1024, 1024, bq);

    // KV = feature @ Wf^T + bf + lora   (2048 x 2048 x 1024)
    mma_gemm<<<dim3(16, 16), 256, MG_SMEM>>>(fhi, flo, wfhi, wflo,
                                             tfh, tfl, bfh, bfl, dKV, 1024, 2048, bfv);

    // att = Q . K^T  batched: M=1024(t), N=256(s), K=64(d)
    sgemm_kernel<128, 8, true><<<dim3(2, 8, 128), 256>>>(
        dQ, dKV, dAtt, 1024, 256, 64, 1024, 2048, 256,
        16,
        1024LL * 1024, 64,
        256LL * 2048, 64,
        16LL * 1024 * 256, 1024LL * 256);

    softmax_kernel<<<16384, 256>>>(dAtt);

    // y = att . V  batched: M=1024(t), N=64(d), K=256(s)
    sgemm_kernel<64, 4, false><<<dim3(1, 8, 128), 256>>>(
        dAtt, dKV + 1024, dY, 1024, 64, 256, 256, 2048, 1024,
        16,
        16LL * 1024 * 256, 1024LL * 256,
        256LL * 2048, 64,
        1024LL * 1024, 64);

    // proj input split + LoRA
    split_kernel<<<(Bsz*Tlen*Cdim/4 + 255)/256, 256>>>((const float4*)dY, (__nv_bfloat162*)yhi, (__nv_bfloat162*)ylo, Bsz*Tlen*Cdim/4);
    lora_t_kernel<<<128, 256>>>(dY, Ap, tph, tpl, SC);

    // out = y @ Wp^T + bp + lora
    mma_gemm<<<dim3(8, 64), 256, MG_SMEM>>>(yhi, ylo, wphi, wplo,
                                            tph, tpl, bph, bpl, out, 1024, 1024, bp);
}

// round 4
// speedup vs baseline: 2.4054x; 1.2179x over previous
#include <cuda_runtime.h>
#include <cuda_bf16.h>
#include <math.h>
#include <stdint.h>

// ---------------------------------------------------------------------------
// CrossAttention with LoRA — round 4: fused tensor attention + split-out proj
// B=8, T=1024, S=256, C=1024, H=16, D=64, R=16, SCALING=1/16
// ---------------------------------------------------------------------------

#define Bsz   8
#define Tlen  1024
#define Slen  256
#define Cdim  1024

// fp32 scratch
__device__ __align__(16) float g_Y [Bsz * Tlen * Cdim];

// bf16 hi/lo splits of activations + weights
__device__ __align__(16) __nv_bfloat16 g_xhi[Bsz*Tlen*Cdim], g_xlo[Bsz*Tlen*Cdim];
__device__ __align__(16) __nv_bfloat16 g_fhi[Bsz*Slen*Cdim], g_flo[Bsz*Slen*Cdim];
__device__ __align__(16) __nv_bfloat16 g_yhi[Bsz*Tlen*Cdim], g_ylo[Bsz*Tlen*Cdim];
__device__ __align__(16) __nv_bfloat16 g_wqhi[Cdim*Cdim],   g_wqlo[Cdim*Cdim];
__device__ __align__(16) __nv_bfloat16 g_wfhi[2*Cdim*Cdim], g_wflo[2*Cdim*Cdim];
__device__ __align__(16) __nv_bfloat16 g_wphi[Cdim*Cdim],   g_wplo[Cdim*Cdim];

// projection outputs in split bf16
__device__ __align__(16) __nv_bfloat16 g_qh[Bsz*Tlen*Cdim],     g_ql[Bsz*Tlen*Cdim];
__device__ __align__(16) __nv_bfloat16 g_kvh[Bsz*Slen*2*Cdim],  g_kvl[Bsz*Slen*2*Cdim];

// LoRA factors in split bf16, K-padded to 32 (cols 16..31 zero)
__device__ __align__(16) __nv_bfloat16 g_tqh[Bsz*Tlen*32], g_tql[Bsz*Tlen*32];
__device__ __align__(16) __nv_bfloat16 g_tfh[Bsz*Slen*32], g_tfl[Bsz*Slen*32];
__device__ __align__(16) __nv_bfloat16 g_tph[Bsz*Tlen*32], g_tpl[Bsz*Tlen*32];
__device__ __align__(16) __nv_bfloat16 g_bqh[Cdim*32],   g_bql[Cdim*32];
__device__ __align__(16) __nv_bfloat16 g_bfh[2*Cdim*32], g_bfl[2*Cdim*32];
__device__ __align__(16) __nv_bfloat16 g_bph[Cdim*32],   g_bpl[Cdim*32];

// ---------------------------------------------------------------------------
// helpers
// ---------------------------------------------------------------------------
__device__ __forceinline__ uint32_t smem_u32(const void* p) {
    uint32_t a;
    asm("{ .reg .u64 t; cvta.to.shared.u64 t, %1; cvt.u32.u64 %0, t; }" : "=r"(a) : "l"(p));
    return a;
}
__device__ __forceinline__ void cp16(uint32_t dst, const void* src) {
    asm volatile("cp.async.cg.shared.global [%0], [%1], 16;" :: "r"(dst), "l"(src));
}
__device__ __forceinline__ void cp_commit() {
    asm volatile("cp.async.commit_group;" ::: "memory");
}
__device__ __forceinline__ void ldm_x4(uint32_t& r0, uint32_t& r1, uint32_t& r2, uint32_t& r3,
                                       uint32_t addr) {
    asm volatile("ldmatrix.sync.aligned.m8n8.x4.shared.b16 {%0,%1,%2,%3}, [%4];"
                 : "=r"(r0), "=r"(r1), "=r"(r2), "=r"(r3) : "r"(addr));
}
__device__ __forceinline__ void ldm_x4t(uint32_t& r0, uint32_t& r1, uint32_t& r2, uint32_t& r3,
                                        uint32_t addr) {
    asm volatile("ldmatrix.sync.aligned.m8n8.x4.trans.shared.b16 {%0,%1,%2,%3}, [%4];"
                 : "=r"(r0), "=r"(r1), "=r"(r2), "=r"(r3) : "r"(addr));
}
__device__ __forceinline__ void mma_bf16(float* c, const uint32_t* a, const uint32_t* b) {
    asm volatile(
        "mma.sync.aligned.m16n8k16.row.col.f32.bf16.bf16.f32 "
        "{%0,%1,%2,%3}, {%4,%5,%6,%7}, {%8,%9}, {%0,%1,%2,%3};"
        : "+f"(c[0]), "+f"(c[1]), "+f"(c[2]), "+f"(c[3])
        : "r"(a[0]), "r"(a[1]), "r"(a[2]), "r"(a[3]), "r"(b[0]), "r"(b[1]));
}
__device__ __forceinline__ __nv_bfloat162 pack_split_hi(float v0, float v1,
                                                        __nv_bfloat16& l0, __nv_bfloat16& l1) {
    __nv_bfloat16 h0 = __float2bfloat16(v0);
    __nv_bfloat16 h1 = __float2bfloat16(v1);
    l0 = __float2bfloat16(v0 - __bfloat162float(h0));
    l1 = __float2bfloat16(v1 - __bfloat162float(h1));
    return __nv_bfloat162(h0, h1);
}

// ---------------------------------------------------------------------------
// fp32 -> (hi, lo) bf16 split
// ---------------------------------------------------------------------------
__global__ void __launch_bounds__(256)
split_kernel(const float4* __restrict__ in, __nv_bfloat162* __restrict__ hi,
             __nv_bfloat162* __restrict__ lo, int n4)
{
    int i = blockIdx.x * 256 + threadIdx.x;
    if (i >= n4) return;
    float4 v = in[i];
    __nv_bfloat16 l0, l1, l2, l3;
    __nv_bfloat162 h01 = pack_split_hi(v.x, v.y, l0, l1);
    __nv_bfloat162 h23 = pack_split_hi(v.z, v.w, l2, l3);
    hi[2*i]   = h01;
    hi[2*i+1] = h23;
    lo[2*i]   = __nv_bfloat162(l0, l1);
    lo[2*i+1] = __nv_bfloat162(l2, l3);
}

// split a (rows x 16) fp32 matrix into (rows x 32) hi/lo bf16, cols 16..31 = 0
__global__ void __launch_bounds__(256)
splitpad_kernel(const float* __restrict__ B, __nv_bfloat16* __restrict__ hi,
                __nv_bfloat16* __restrict__ lo, int rows)
{
    int row = blockIdx.x * 256 + threadIdx.x;
    if (row >= rows) return;
#pragma unroll
    for (int j = 0; j < 16; j++) {
        float v = B[row * 16 + j];
        __nv_bfloat16 h = __float2bfloat16(v);
        __nv_bfloat16 l = __float2bfloat16(v - __bfloat162float(h));
        hi[row * 32 + j] = h;
        lo[row * 32 + j] = l;
        hi[row * 32 + 16 + j] = __float2bfloat16(0.0f);
        lo[row * 32 + 16 + j] = __float2bfloat16(0.0f);
    }
}

// ---------------------------------------------------------------------------
// LoRA intermediate: T[m,r] = scale * sum_k X[m,k] * Amat[r,k], split bf16,
// padded to 32 cols.
// ---------------------------------------------------------------------------
__global__ void __launch_bounds__(256)
lora_t_kernel(const float* __restrict__ X, const float* __restrict__ Amat,
              __nv_bfloat16* __restrict__ Thi, __nv_bfloat16* __restrict__ Tlo,
              float scale)
{
    __shared__ float xs[64][68];
    __shared__ float as_[16][65];

    const int tid = threadIdx.x;
    const int bm  = blockIdx.x * 64;
    const int r   = tid & 15;
    const int mg  = tid >> 4;

    float a0 = 0.f, a1 = 0.f, a2 = 0.f, a3 = 0.f;

    for (int kt = 0; kt < 1024; kt += 64) {
#pragma unroll
        for (int i = tid; i < 1024; i += 256) {
            int row = i >> 4, c4 = i & 15;
            float4 v = *reinterpret_cast<const float4*>(
                &X[(long long)(bm + row) * 1024 + kt + c4 * 4]);
            *reinterpret_cast<float4*>(&xs[row][c4 * 4]) = v;
        }
#pragma unroll
        for (int i = tid; i < 1024; i += 256) {
            int row = i >> 6, kk = i & 63;
            as_[row][kk] = Amat[row * 1024 + kt + kk];
        }
        __syncthreads();
#pragma unroll 16
        for (int kk = 0; kk < 64; kk++) {
            float a = as_[r][kk];
            a0 = fmaf(xs[mg * 4 + 0][kk], a, a0);
            a1 = fmaf(xs[mg * 4 + 1][kk], a, a1);
            a2 = fmaf(xs[mg * 4 + 2][kk], a, a2);
            a3 = fmaf(xs[mg * 4 + 3][kk], a, a3);
        }
        __syncthreads();
    }
    const __nv_bfloat16 z = __float2bfloat16(0.0f);
#pragma unroll
    for (int q = 0; q < 4; q++) {
        float v = (q == 0 ? a0 : q == 1 ? a1 : q == 2 ? a2 : a3) * scale;
        long long row = bm + mg * 4 + q;
        __nv_bfloat16 h = __float2bfloat16(v);
        __nv_bfloat16 l = __float2bfloat16(v - __bfloat162float(h));
        Thi[row * 32 + r] = h;       Tlo[row * 32 + r] = l;
        Thi[row * 32 + 16 + r] = z;  Tlo[row * 32 + 16 + r] = z;
    }
}

// ---------------------------------------------------------------------------
// split-bf16 mma.sync GEMM, C = A*B^T + bias + LoRA (folded in K-loop).
// SPLIT_OUT=false: fp32 C.  SPLIT_OUT=true: split-bf16 Chi/Clo.
// ---------------------------------------------------------------------------
#define MG_STAGE 32768
#define MG_SMEM  (2 * MG_STAGE)

template<bool SPLIT_OUT>
__global__ void __launch_bounds__(256)
mma_gemm(const __nv_bfloat16* __restrict__ Ahi, const __nv_bfloat16* __restrict__ Alo,
         const __nv_bfloat16* __restrict__ Bhi, const __nv_bfloat16* __restrict__ Blo,
         const __nv_bfloat16* __restrict__ LThi, const __nv_bfloat16* __restrict__ LTlo,
         const __nv_bfloat16* __restrict__ LBhi, const __nv_bfloat16* __restrict__ LBlo,
         float* __restrict__ C, __nv_bfloat16* __restrict__ Chi,
         __nv_bfloat16* __restrict__ Clo,
         int K, int N, const float* __restrict__ bias)
{
    extern __shared__ char smem[];
    const uint32_t sb = smem_u32(smem);
    const int tid  = threadIdx.x;
    const int lane = tid & 31;
    const int warp = tid >> 5;
    const int wm   = warp >> 1;
    const int wn   = warp & 1;
    const int bm = blockIdx.y * 128;
    const int bn = blockIdx.x * 128;

    const int KCH = K >> 5;
    const int NC  = KCH + 1;

    float acc[2][8][4];
#pragma unroll
    for (int m = 0; m < 2; m++)
#pragma unroll
        for (int n = 0; n < 8; n++)
#pragma unroll
            for (int j = 0; j < 4; j++) acc[m][n][j] = 0.0f;

    auto load_chunk = [&](int ch, int st) {
        const bool lora = (ch == KCH);
        const int kt = ch << 5;
#pragma unroll
        for (int i = tid; i < 2048; i += 256) {
            int tile = i >> 9;
            int idx  = i & 511;
            int row  = idx >> 2;
            int c4   = idx & 3;
            const __nv_bfloat16* g;
            long long off;
            if (!lora) {
                g = (tile == 0) ? Ahi : (tile == 1) ? Alo : (tile == 2) ? Bhi : Blo;
                int r0 = (tile < 2) ? bm : bn;
                off = (long long)(r0 + row) * K + kt + c4 * 8;
            } else {
                g = (tile == 0) ? LThi : (tile == 1) ? LTlo : (tile == 2) ? LBhi : LBlo;
                int r0 = (tile < 2) ? bm : bn;
                off = (long long)(r0 + row) * 32 + c4 * 8;
            }
            uint32_t dst = sb + st * MG_STAGE + tile * 8192 + row * 64
                         + ((c4 ^ ((row >> 1) & 3)) << 4);
            cp16(dst, g + off);
        }
        cp_commit();
    };

    load_chunk(0, 0);

    for (int ch = 0; ch < NC; ch++) {
        const int st = ch & 1;
        if (ch + 1 < NC) {
            load_chunk(ch + 1, st ^ 1);
            asm volatile("cp.async.wait_group 1;" ::: "memory");
        } else {
            asm volatile("cp.async.wait_group 0;" ::: "memory");
        }
        __syncthreads();

        const uint32_t stb = sb + st * MG_STAGE;
#pragma unroll
        for (int kk = 0; kk < 2; kk++) {
            uint32_t ah[2][4], al[2][4];
#pragma unroll
            for (int mf = 0; mf < 2; mf++) {
                int row = wm * 32 + mf * 16 + (lane & 15);
                int c4  = kk * 2 + (lane >> 4);
                uint32_t sw = (uint32_t)((c4 ^ ((row >> 1) & 3)) << 4);
                uint32_t ad = stb + row * 64 + sw;
                ldm_x4(ah[mf][0], ah[mf][1], ah[mf][2], ah[mf][3], ad);
                ldm_x4(al[mf][0], al[mf][1], al[mf][2], al[mf][3], ad + 8192);
            }
            uint32_t bh[8][2], bl[8][2];
#pragma unroll
            for (int p = 0; p < 4; p++) {
                int row = wn * 64 + p * 16 + (lane & 15);
                int c4  = kk * 2 + (lane >> 4);
                uint32_t sw = (uint32_t)((c4 ^ ((row >> 1) & 3)) << 4);
                uint32_t ad = stb + 16384 + row * 64 + sw;
                uint32_t r0, r1, r2, r3;
                ldm_x4(r0, r1, r2, r3, ad);
                bh[2*p][0] = r0; bh[2*p][1] = r2;
                bh[2*p+1][0] = r1; bh[2*p+1][1] = r3;
                ldm_x4(r0, r1, r2, r3, ad + 8192);
                bl[2*p][0] = r0; bl[2*p][1] = r2;
                bl[2*p+1][0] = r1; bl[2*p+1][1] = r3;
            }
#pragma unroll
            for (int mf = 0; mf < 2; mf++)
#pragma unroll
                for (int n = 0; n < 8; n++) {
                    mma_bf16(acc[mf][n], ah[mf], bh[n]);
                    mma_bf16(acc[mf][n], ah[mf], bl[n]);
                    mma_bf16(acc[mf][n], al[mf], bh[n]);
                }
        }
        __syncthreads();
    }

    // ---- epilogue ----
#pragma unroll
    for (int mf = 0; mf < 2; mf++) {
        int r1 = bm + wm * 32 + mf * 16 + (lane >> 2);
#pragma unroll
        for (int n = 0; n < 8; n++) {
            int col = bn + wn * 64 + n * 8 + (lane & 3) * 2;
            float b0 = bias[col], b1 = bias[col + 1];
            float v00 = acc[mf][n][0] + b0, v01 = acc[mf][n][1] + b1;
            float v10 = acc[mf][n][2] + b0, v11 = acc[mf][n][3] + b1;
            if (SPLIT_OUT) {
                __nv_bfloat16 l0, l1;
                __nv_bfloat162 h = pack_split_hi(v00, v01, l0, l1);
                *reinterpret_cast<__nv_bfloat162*>(&Chi[(long long)r1 * N + col]) = h;
                *reinterpret_cast<__nv_bfloat162*>(&Clo[(long long)r1 * N + col]) =
                    __nv_bfloat162(l0, l1);
                h = pack_split_hi(v10, v11, l0, l1);
                *reinterpret_cast<__nv_bfloat162*>(&Chi[(long long)(r1 + 8) * N + col]) = h;
                *reinterpret_cast<__nv_bfloat162*>(&Clo[(long long)(r1 + 8) * N + col]) =
                    __nv_bfloat162(l0, l1);
            } else {
                *reinterpret_cast<float2*>(&C[(long long)r1 * N + col]) =
                    make_float2(v00, v01);
                *reinterpret_cast<float2*>(&C[(long long)(r1 + 8) * N + col]) =
                    make_float2(v10, v11);
            }
        }
    }
}

// ---------------------------------------------------------------------------
// Fused attention: per (b, h, 64-row t-tile)
//   S = Q K^T / 8, causal mask, softmax, Y = P V   (all split-bf16 mma)
// grid = (T/64, B*H), 256 threads.
// smem: Qh@0(8K) Ql@8K Kh@16K(32K) Kl@48K  [reused: Ph@0(32K) Pl@32K]
//       Vh@80K(32K) Vl@112K  red_max@144K(1K) red_sum@145K(1K)
// ---------------------------------------------------------------------------
#define FA_V_H   81920
#define FA_V_L   114688
#define FA_REDM  147456
#define FA_REDS  148480
#define FA_SMEM  149504

__global__ void __launch_bounds__(256)
fa_kernel(const __nv_bfloat16* __restrict__ Qh, const __nv_bfloat16* __restrict__ Ql,
          const __nv_bfloat16* __restrict__ KVh, const __nv_bfloat16* __restrict__ KVl,
          float* __restrict__ Y)
{
    extern __shared__ char smem[];
    const uint32_t sb = smem_u32(smem);
    const int tid  = threadIdx.x;
    const int lane = tid & 31;
    const int warp = tid >> 5;
    const int bh = blockIdx.y;
    const int b = bh >> 4, h = bh & 15;
    const int t0 = blockIdx.x * 64;

    // ---- async loads of Q, K, V (hi/lo), SW-swizzled 128B rows ----
    {
        const long long qbase = ((long long)(b * 1024 + t0)) * 1024 + h * 64;
#pragma unroll
        for (int i = tid; i < 512; i += 256) {
            int row = i >> 3, c = i & 7;
            uint32_t sw = (uint32_t)((c ^ (row & 7)) << 4);
            cp16(sb + row * 128 + sw,        Qh + qbase + (long long)row * 1024 + c * 8);
            cp16(sb + 8192 + row * 128 + sw, Ql + qbase + (long long)row * 1024 + c * 8);
        }
        const long long kbase = ((long long)(b * 256)) * 2048 + h * 64;
        const long long vbase = kbase + 1024;
#pragma unroll
        for (int i = tid; i < 2048; i += 256) {
            int row = i >> 3, c = i & 7;
            uint32_t sw = (uint32_t)((c ^ (row & 7)) << 4);
            long long go = (long long)row * 2048 + c * 8;
            cp16(sb + 16384  + row * 128 + sw, KVh + kbase + go);
            cp16(sb + 49152  + row * 128 + sw, KVl + kbase + go);
            cp16(sb + FA_V_H + row * 128 + sw, KVh + vbase + go);
            cp16(sb + FA_V_L + row * 128 + sw, KVl + vbase + go);
        }
        cp_commit();
        asm volatile("cp.async.wait_group 0;" ::: "memory");
    }
    __syncthreads();

    const int rq = lane >> 2, cq = lane & 3;

    // ---- phase 1: S = Q K^T (M=64, N=256, K=64), warp tile 32x64 ----
    const int wm = warp >> 2;   // 0..1
    const int wn = warp & 3;    // 0..3
    float acc[2][8][4];
#pragma unroll
    for (int m = 0; m < 2; m++)
#pragma unroll
        for (int n = 0; n < 8; n++)
#pragma unroll
            for (int j = 0; j < 4; j++) acc[m][n][j] = 0.0f;

#pragma unroll
    for (int ks = 0; ks < 4; ks++) {
        uint32_t ah[2][4], al[2][4];
#pragma unroll
        for (int mf = 0; mf < 2; mf++) {
            int row = wm * 32 + mf * 16 + (lane & 15);
            int ch  = ks * 2 + (lane >> 4);
            uint32_t ad = sb + row * 128 + (uint32_t)((ch ^ (row & 7)) << 4);
            ldm_x4(ah[mf][0], ah[mf][1], ah[mf][2], ah[mf][3], ad);
            ldm_x4(al[mf][0], al[mf][1], al[mf][2], al[mf][3], ad + 8192);
        }
        uint32_t bh_[8][2], bl_[8][2];
#pragma unroll
        for (int p = 0; p < 4; p++) {
            int row = wn * 64 + p * 16 + (lane & 15);
            int ch  = ks * 2 + (lane >> 4);
            uint32_t ad = sb + 16384 + row * 128 + (uint32_t)((ch ^ (row & 7)) << 4);
            uint32_t r0, r1, r2, r3;
            ldm_x4(r0, r1, r2, r3, ad);
            bh_[2*p][0] = r0; bh_[2*p][1] = r2;
            bh_[2*p+1][0] = r1; bh_[2*p+1][1] = r3;
            ldm_x4(r0, r1, r2, r3, ad + 32768);
            bl_[2*p][0] = r0; bl_[2*p][1] = r2;
            bl_[2*p+1][0] = r1; bl_[2*p+1][1] = r3;
        }
#pragma unroll
        for (int mf = 0; mf < 2; mf++)
#pragma unroll
            for (int n = 0; n < 8; n++) {
                mma_bf16(acc[mf][n], ah[mf], bh_[n]);
                mma_bf16(acc[mf][n], ah[mf], bl_[n]);
                mma_bf16(acc[mf][n], al[mf], bh_[n]);
            }
    }

    // ---- softmax (rows split over 4 n-warps, reduce via smem) ----
    float* red_max = reinterpret_cast<float*>(smem + FA_REDM);
    float* red_sum = reinterpret_cast<float*>(smem + FA_REDS);
    const bool need_mask = (t0 < Slen);

#pragma unroll
    for (int mf = 0; mf < 2; mf++)
#pragma unroll
        for (int sub = 0; sub < 2; sub++) {
            int rl = wm * 32 + mf * 16 + sub * 8 + rq;
            int trow = t0 + rl;
            float m = -1e30f;
#pragma unroll
            for (int nf = 0; nf < 8; nf++) {
                int col = wn * 64 + nf * 8 + cq * 2;
                float v0 = acc[mf][nf][sub*2]     * 0.125f;
                float v1 = acc[mf][nf][sub*2 + 1] * 0.125f;
                if (need_mask) {
                    if (col     > trow) v0 = -1e30f;
                    if (col + 1 > trow) v1 = -1e30f;
                }
                acc[mf][nf][sub*2]     = v0;
                acc[mf][nf][sub*2 + 1] = v1;
                m = fmaxf(m, fmaxf(v0, v1));
            }
            m = fmaxf(m, __shfl_xor_sync(0xffffffffu, m, 1));
            m = fmaxf(m, __shfl_xor_sync(0xffffffffu, m, 2));
            if (cq == 0) red_max[wn * 64 + rl] = m;
        }
    __syncthreads();

#pragma unroll
    for (int mf = 0; mf < 2; mf++)
#pragma unroll
        for (int sub = 0; sub < 2; sub++) {
            int rl = wm * 32 + mf * 16 + sub * 8 + rq;
            float M = fmaxf(fmaxf(red_max[rl], red_max[64 + rl]),
                            fmaxf(red_max[128 + rl], red_max[192 + rl]));
            float s = 0.0f;
#pragma unroll
            for (int nf = 0; nf < 8; nf++) {
                float e0 = __expf(acc[mf][nf][sub*2]     - M);
                float e1 = __expf(acc[mf][nf][sub*2 + 1] - M);
                acc[mf][nf][sub*2]     = e0;
                acc[mf][nf][sub*2 + 1] = e1;
                s += e0 + e1;
            }
            s += __shfl_xor_sync(0xffffffffu, s, 1);
            s += __shfl_xor_sync(0xffffffffu, s, 2);
            if (cq == 0) red_sum[wn * 64 + rl] = s;
        }
    __syncthreads();

    // ---- store P (unnormalized) as split bf16 into smem @0 / @32768 ----
#pragma unroll
    for (int mf = 0; mf < 2; mf++)
#pragma unroll
        for (int sub = 0; sub < 2; sub++) {
            int rl = wm * 32 + mf * 16 + sub * 8 + rq;
#pragma unroll
            for (int nf = 0; nf < 8; nf++) {
                int col = wn * 64 + nf * 8 + cq * 2;
                __nv_bfloat16 l0, l1;
                __nv_bfloat162 hh = pack_split_hi(acc[mf][nf][sub*2],
                                                  acc[mf][nf][sub*2 + 1], l0, l1);
                int chnk = col >> 3;
                uint32_t off = (uint32_t)(rl * 512 + ((chnk ^ (rl & 7)) << 4) + (col & 7) * 2);
                *reinterpret_cast<__nv_bfloat162*>(smem + off) = hh;
                *reinterpret_cast<__nv_bfloat162*>(smem + 32768 + off) = __nv_bfloat162(l0, l1);
            }
        }
    __syncthreads();

    // ---- phase 2: Y = P V (M=64, N=64, K=256), warp tile 32x16 ----
    const int wm2 = warp >> 2;  // 0..1
    const int wn2 = warp & 3;   // 0..3
    float acc2[2][2][4];
#pragma unroll
    for (int m = 0; m < 2; m++)
#pragma unroll
        for (int n = 0; n < 2; n++)
#pragma unroll
            for (int j = 0; j < 4; j++) acc2[m][n][j] = 0.0f;

#pragma unroll
    for (int ks = 0; ks < 16; ks++) {
        uint32_t ph[2][4], pl[2][4];
#pragma unroll
        for (int mf = 0; mf < 2; mf++) {
            int row = wm2 * 32 + mf * 16 + (lane & 15);
            int ch  = ks * 2 + (lane >> 4);
            uint32_t ad = sb + row * 512 + (uint32_t)((ch ^ (row & 7)) << 4);
            ldm_x4(ph[mf][0], ph[mf][1], ph[mf][2], ph[mf][3], ad);
            ldm_x4(pl[mf][0], pl[mf][1], pl[mf][2], pl[mf][3], ad + 32768);
        }
        uint32_t vh_[2][2], vl_[2][2];
        {
            int g = lane >> 3;
            int srow = ks * 16 + (g & 1) * 8 + (lane & 7);
            int dch  = wn2 * 2 + (g >> 1);
            uint32_t ad = sb + FA_V_H + srow * 128 + (uint32_t)((dch ^ (srow & 7)) << 4);
            uint32_t r0, r1, r2, r3;
            ldm_x4t(r0, r1, r2, r3, ad);
            vh_[0][0] = r0; vh_[0][1] = r1; vh_[1][0] = r2; vh_[1][1] = r3;
            ldm_x4t(r0, r1, r2, r3, ad + 32768);
            vl_[0][0] = r0; vl_[0][1] = r1; vl_[1][0] = r2; vl_[1][1] = r3;
        }
#pragma unroll
        for (int mf = 0; mf < 2; mf++)
#pragma unroll
            for (int nf = 0; nf < 2; nf++) {
                mma_bf16(acc2[mf][nf], ph[mf], vh_[nf]);
                mma_bf16(acc2[mf][nf], ph[mf], vl_[nf]);
                mma_bf16(acc2[mf][nf], pl[mf], vh_[nf]);
            }
    }

    // ---- epilogue: divide by row sum, store fp32 Y ----
#pragma unroll
    for (int mf = 0; mf < 2; mf++)
#pragma unroll
        for (int sub = 0; sub < 2; sub++) {
            int rl = wm2 * 32 + mf * 16 + sub * 8 + rq;
            float inv = 1.0f / (red_sum[rl] + red_sum[64 + rl] +
                                red_sum[128 + rl] + red_sum[192 + rl]);
            long long yo = ((long long)(b * 1024 + t0 + rl)) * 1024 + h * 64;
#pragma unroll
            for (int nf = 0; nf < 2; nf++) {
                int col = wn2 * 16 + nf * 8 + cq * 2;
                *reinterpret_cast<float2*>(Y + yo + col) =
                    make_float2(acc2[mf][nf][sub*2] * inv, acc2[mf][nf][sub*2 + 1] * inv);
            }
        }
}

// ---------------------------------------------------------------------------
// Launch
// ---------------------------------------------------------------------------
extern "C" void kernel_launch(void* const* d_in, const int* in_sizes, int n_in,
                              void* d_out, int out_size)
{
    const float* x  = (const float*)d_in[0];
    const float* ft = (const float*)d_in[1];
    const float* Wq = (const float*)d_in[2];
    const float* bq = (const float*)d_in[3];
    const float* Aq = (const float*)d_in[4];
    const float* Bq = (const float*)d_in[5];
    const float* Wf = (const float*)d_in[6];
    const float* bfv= (const float*)d_in[7];
    const float* Af = (const float*)d_in[8];
    const float* Bf = (const float*)d_in[9];
    const float* Wp = (const float*)d_in[10];
    const float* bp = (const float*)d_in[11];
    const float* Ap = (const float*)d_in[12];
    const float* Bp = (const float*)d_in[13];
    float* out = (float*)d_out;

    float* dY;
    cudaGetSymbolAddress((void**)&dY, g_Y);

    __nv_bfloat16 *xhi, *xlo, *fhi, *flo, *yhi, *ylo;
    __nv_bfloat16 *wqhi, *wqlo, *wfhi, *wflo, *wphi, *wplo;
    __nv_bfloat16 *qh, *ql, *kvh, *kvl;
    __nv_bfloat16 *tqh, *tql, *tfh, *tfl, *tph, *tpl;
    __nv_bfloat16 *bqh, *bql, *bfh, *bfl, *bph, *bpl;
    cudaGetSymbolAddress((void**)&xhi, g_xhi);  cudaGetSymbolAddress((void**)&xlo, g_xlo);
    cudaGetSymbolAddress((void**)&fhi, g_fhi);  cudaGetSymbolAddress((void**)&flo, g_flo);
    cudaGetSymbolAddress((void**)&yhi, g_yhi);  cudaGetSymbolAddress((void**)&ylo, g_ylo);
    cudaGetSymbolAddress((void**)&wqhi, g_wqhi); cudaGetSymbolAddress((void**)&wqlo, g_wqlo);
    cudaGetSymbolAddress((void**)&wfhi, g_wfhi); cudaGetSymbolAddress((void**)&wflo, g_wflo);
    cudaGetSymbolAddress((void**)&wphi, g_wphi); cudaGetSymbolAddress((void**)&wplo, g_wplo);
    cudaGetSymbolAddress((void**)&qh, g_qh);    cudaGetSymbolAddress((void**)&ql, g_ql);
    cudaGetSymbolAddress((void**)&kvh, g_kvh);  cudaGetSymbolAddress((void**)&kvl, g_kvl);
    cudaGetSymbolAddress((void**)&tqh, g_tqh);  cudaGetSymbolAddress((void**)&tql, g_tql);
    cudaGetSymbolAddress((void**)&tfh, g_tfh);  cudaGetSymbolAddress((void**)&tfl, g_tfl);
    cudaGetSymbolAddress((void**)&tph, g_tph);  cudaGetSymbolAddress((void**)&tpl, g_tpl);
    cudaGetSymbolAddress((void**)&bqh, g_bqh);  cudaGetSymbolAddress((void**)&bql, g_bql);
    cudaGetSymbolAddress((void**)&bfh, g_bfh);  cudaGetSymbolAddress((void**)&bfl, g_bfl);
    cudaGetSymbolAddress((void**)&bph, g_bph);  cudaGetSymbolAddress((void**)&bpl, g_bpl);

    cudaFuncSetAttribute(mma_gemm<false>, cudaFuncAttributeMaxDynamicSharedMemorySize, MG_SMEM);
    cudaFuncSetAttribute(mma_gemm<true>,  cudaFuncAttributeMaxDynamicSharedMemorySize, MG_SMEM);
    cudaFuncSetAttribute(fa_kernel, cudaFuncAttributeMaxDynamicSharedMemorySize, FA_SMEM);

    const float SC = 1.0f / 16.0f;

    // splits
    split_kernel<<<(Bsz*Tlen*Cdim/4 + 255)/256, 256>>>((const float4*)x,  (__nv_bfloat162*)xhi,  (__nv_bfloat162*)xlo,  Bsz*Tlen*Cdim/4);
    split_kernel<<<(Cdim*Cdim/4 + 255)/256, 256>>>((const float4*)Wq, (__nv_bfloat162*)wqhi, (__nv_bfloat162*)wqlo, Cdim*Cdim/4);
    split_kernel<<<(Bsz*Slen*Cdim/4 + 255)/256, 256>>>((const float4*)ft, (__nv_bfloat162*)fhi,  (__nv_bfloat162*)flo,  Bsz*Slen*Cdim/4);
    split_kernel<<<(2*Cdim*Cdim/4 + 255)/256, 256>>>((const float4*)Wf, (__nv_bfloat162*)wfhi, (__nv_bfloat162*)wflo, 2*Cdim*Cdim/4);
    split_kernel<<<(Cdim*Cdim/4 + 255)/256, 256>>>((const float4*)Wp, (__nv_bfloat162*)wphi, (__nv_bfloat162*)wplo, Cdim*Cdim/4);

    // LoRA factors
    lora_t_kernel<<<128, 256>>>(x, Aq, tqh, tql, SC);
    lora_t_kernel<<<32, 256>>>(ft, Af, tfh, tfl, SC);
    splitpad_kernel<<<(Cdim + 255)/256, 256>>>(Bq, bqh, bql, Cdim);
    splitpad_kernel<<<(2*Cdim + 255)/256, 256>>>(Bf, bfh, bfl, 2*Cdim);
    splitpad_kernel<<<(Cdim + 255)/256, 256>>>(Bp, bph, bpl, Cdim);

    // Q projection -> split bf16  (8192 x 1024 x 1024)
    mma_gemm<true><<<dim3(8, 64), 256, MG_SMEM>>>(xhi, xlo, wqhi, wqlo,
        tqh, tql, bqh, bql, nullptr, qh, ql, 1024, 1024, bq);

    // KV projection -> split bf16  (2048 x 2048 x 1024)
    mma_gemm<true><<<dim3(16, 16), 256, MG_SMEM>>>(fhi, flo, wfhi, wflo,
        tfh, tfl, bfh, bfl, nullptr, kvh, kvl, 1024, 2048, bfv);

    // fused attention -> Y fp32
    fa_kernel<<<dim3(16, 128), 256, FA_SMEM>>>(qh, ql, kvh, kvl, dY);

    // proj input split + LoRA
    split_kernel<<<(Bsz*Tlen*Cdim/4 + 255)/256, 256>>>((const float4*)dY, (__nv_bfloat162*)yhi, (__nv_bfloat162*)ylo, Bsz*Tlen*Cdim/4);
    lora_t_kernel<<<128, 256>>>(dY, Ap, tph, tpl, SC);

    // out = y @ Wp^T + bp + lora  (fp32 out)
    mma_gemm<false><<<dim3(8, 64), 256, MG_SMEM>>>(yhi, ylo, wphi, wplo,
        tph, tpl, bph, bpl, out, nullptr, nullptr, 1024, 1024, bp);
}

// round 5
// speedup vs baseline: 2.4612x; 1.0232x over previous
#include <cuda_runtime.h>
#include <cuda_bf16.h>
#include <math.h>
#include <stdint.h>

// ---------------------------------------------------------------------------
// CrossAttention with LoRA — round 5
// fa->split out, causal skip, 3-stage GEMM pipeline, merged prep
// B=8, T=1024, S=256, C=1024, H=16, D=64, R=16, SCALING=1/16
// ---------------------------------------------------------------------------

#define Bsz   8
#define Tlen  1024
#define Slen  256
#define Cdim  1024

// bf16 hi/lo splits of activations + weights
__device__ __align__(16) __nv_bfloat16 g_xhi[Bsz*Tlen*Cdim], g_xlo[Bsz*Tlen*Cdim];
__device__ __align__(16) __nv_bfloat16 g_fhi[Bsz*Slen*Cdim], g_flo[Bsz*Slen*Cdim];
__device__ __align__(16) __nv_bfloat16 g_yhi[Bsz*Tlen*Cdim], g_ylo[Bsz*Tlen*Cdim];
__device__ __align__(16) __nv_bfloat16 g_wqhi[Cdim*Cdim],   g_wqlo[Cdim*Cdim];
__device__ __align__(16) __nv_bfloat16 g_wfhi[2*Cdim*Cdim], g_wflo[2*Cdim*Cdim];
__device__ __align__(16) __nv_bfloat16 g_wphi[Cdim*Cdim],   g_wplo[Cdim*Cdim];

// projection outputs in split bf16
__device__ __align__(16) __nv_bfloat16 g_qh[Bsz*Tlen*Cdim],     g_ql[Bsz*Tlen*Cdim];
__device__ __align__(16) __nv_bfloat16 g_kvh[Bsz*Slen*2*Cdim],  g_kvl[Bsz*Slen*2*Cdim];

// LoRA factors in split bf16, K-padded to 32 (cols 16..31 zero)
__device__ __align__(16) __nv_bfloat16 g_tqh[Bsz*Tlen*32], g_tql[Bsz*Tlen*32];
__device__ __align__(16) __nv_bfloat16 g_tfh[Bsz*Slen*32], g_tfl[Bsz*Slen*32];
__device__ __align__(16) __nv_bfloat16 g_tph[Bsz*Tlen*32], g_tpl[Bsz*Tlen*32];
__device__ __align__(16) __nv_bfloat16 g_bqh[Cdim*32],   g_bql[Cdim*32];
__device__ __align__(16) __nv_bfloat16 g_bfh[2*Cdim*32], g_bfl[2*Cdim*32];
__device__ __align__(16) __nv_bfloat16 g_bph[Cdim*32],   g_bpl[Cdim*32];

// ---------------------------------------------------------------------------
// helpers
// ---------------------------------------------------------------------------
__device__ __forceinline__ uint32_t smem_u32(const void* p) {
    uint32_t a;
    asm("{ .reg .u64 t; cvta.to.shared.u64 t, %1; cvt.u32.u64 %0, t; }" : "=r"(a) : "l"(p));
    return a;
}
__device__ __forceinline__ void cp16(uint32_t dst, const void* src) {
    asm volatile("cp.async.cg.shared.global [%0], [%1], 16;" :: "r"(dst), "l"(src));
}
__device__ __forceinline__ void cp_commit() {
    asm volatile("cp.async.commit_group;" ::: "memory");
}
__device__ __forceinline__ void ldm_x4(uint32_t& r0, uint32_t& r1, uint32_t& r2, uint32_t& r3,
                                       uint32_t addr) {
    asm volatile("ldmatrix.sync.aligned.m8n8.x4.shared.b16 {%0,%1,%2,%3}, [%4];"
                 : "=r"(r0), "=r"(r1), "=r"(r2), "=r"(r3) : "r"(addr));
}
__device__ __forceinline__ void ldm_x4t(uint32_t& r0, uint32_t& r1, uint32_t& r2, uint32_t& r3,
                                        uint32_t addr) {
    asm volatile("ldmatrix.sync.aligned.m8n8.x4.trans.shared.b16 {%0,%1,%2,%3}, [%4];"
                 : "=r"(r0), "=r"(r1), "=r"(r2), "=r"(r3) : "r"(addr));
}
__device__ __forceinline__ void mma_bf16(float* c, const uint32_t* a, const uint32_t* b) {
    asm volatile(
        "mma.sync.aligned.m16n8k16.row.col.f32.bf16.bf16.f32 "
        "{%0,%1,%2,%3}, {%4,%5,%6,%7}, {%8,%9}, {%0,%1,%2,%3};"
        : "+f"(c[0]), "+f"(c[1]), "+f"(c[2]), "+f"(c[3])
        : "r"(a[0]), "r"(a[1]), "r"(a[2]), "r"(a[3]), "r"(b[0]), "r"(b[1]));
}
__device__ __forceinline__ __nv_bfloat162 pack_split_hi(float v0, float v1,
                                                        __nv_bfloat16& l0, __nv_bfloat16& l1) {
    __nv_bfloat16 h0 = __float2bfloat16(v0);
    __nv_bfloat16 h1 = __float2bfloat16(v1);
    l0 = __float2bfloat16(v0 - __bfloat162float(h0));
    l1 = __float2bfloat16(v1 - __bfloat162float(h1));
    return __nv_bfloat162(h0, h1);
}

// ---------------------------------------------------------------------------
// merged fp32 -> (hi, lo) split over 5 tensors in one launch
// segment sizes (in float4): x 2097152/4*... computed below
// ---------------------------------------------------------------------------
#define SEG0 (Bsz*Tlen*Cdim/4)                 // x       : 2097152
#define SEG1 (SEG0 + Cdim*Cdim/4)              // + Wq    : 262144
#define SEG2 (SEG1 + Bsz*Slen*Cdim/4)          // + ft    : 524288
#define SEG3 (SEG2 + 2*Cdim*Cdim/4)            // + Wf    : 524288
#define SEG4 (SEG3 + Cdim*Cdim/4)              // + Wp    : 262144

__global__ void __launch_bounds__(256)
split_multi(const float4* __restrict__ x,  const float4* __restrict__ Wq,
            const float4* __restrict__ ft, const float4* __restrict__ Wf,
            const float4* __restrict__ Wp,
            __nv_bfloat162* __restrict__ xhi,  __nv_bfloat162* __restrict__ xlo,
            __nv_bfloat162* __restrict__ wqhi, __nv_bfloat162* __restrict__ wqlo,
            __nv_bfloat162* __restrict__ fhi,  __nv_bfloat162* __restrict__ flo,
            __nv_bfloat162* __restrict__ wfhi, __nv_bfloat162* __restrict__ wflo,
            __nv_bfloat162* __restrict__ wphi, __nv_bfloat162* __restrict__ wplo)
{
    int gi = blockIdx.x * 256 + threadIdx.x;
    if (gi >= SEG4) return;
    const float4* in; __nv_bfloat162* hi; __nv_bfloat162* lo; int i;
    if (gi < SEG0)      { in = x;  hi = xhi;  lo = xlo;  i = gi; }
    else if (gi < SEG1) { in = Wq; hi = wqhi; lo = wqlo; i = gi - SEG0; }
    else if (gi < SEG2) { in = ft; hi = fhi;  lo = flo;  i = gi - SEG1; }
    else if (gi < SEG3) { in = Wf; hi = wfhi; lo = wflo; i = gi - SEG2; }
    else                { in = Wp; hi = wphi; lo = wplo; i = gi - SEG3; }
    float4 v = in[i];
    __nv_bfloat16 l0, l1, l2, l3;
    __nv_bfloat162 h01 = pack_split_hi(v.x, v.y, l0, l1);
    __nv_bfloat162 h23 = pack_split_hi(v.z, v.w, l2, l3);
    hi[2*i]   = h01;
    hi[2*i+1] = h23;
    lo[2*i]   = __nv_bfloat162(l0, l1);
    lo[2*i+1] = __nv_bfloat162(l2, l3);
}

// merged splitpad for Bq (1024 rows), Bf (2048), Bp (1024): rows x16 fp32
// -> rows x32 split bf16, cols 16..31 zero
__global__ void __launch_bounds__(256)
splitpad_multi(const float* __restrict__ Bq, const float* __restrict__ Bf,
               const float* __restrict__ Bp,
               __nv_bfloat16* __restrict__ qh, __nv_bfloat16* __restrict__ ql,
               __nv_bfloat16* __restrict__ fh, __nv_bfloat16* __restrict__ fl,
               __nv_bfloat16* __restrict__ ph, __nv_bfloat16* __restrict__ pl)
{
    int g = blockIdx.x * 256 + threadIdx.x;
    if (g >= 4096) return;
    const float* B; __nv_bfloat16* hi; __nv_bfloat16* lo; int row;
    if (g < 1024)      { B = Bq; hi = qh; lo = ql; row = g; }
    else if (g < 3072) { B = Bf; hi = fh; lo = fl; row = g - 1024; }
    else               { B = Bp; hi = ph; lo = pl; row = g - 3072; }
#pragma unroll
    for (int j = 0; j < 16; j++) {
        float v = B[row * 16 + j];
        __nv_bfloat16 h = __float2bfloat16(v);
        __nv_bfloat16 l = __float2bfloat16(v - __bfloat162float(h));
        hi[row * 32 + j] = h;
        lo[row * 32 + j] = l;
        hi[row * 32 + 16 + j] = __float2bfloat16(0.0f);
        lo[row * 32 + 16 + j] = __float2bfloat16(0.0f);
    }
}

// ---------------------------------------------------------------------------
// LoRA intermediate from fp32 X
// ---------------------------------------------------------------------------
__global__ void __launch_bounds__(256)
lora_t_kernel(const float* __restrict__ X, const float* __restrict__ Amat,
              __nv_bfloat16* __restrict__ Thi, __nv_bfloat16* __restrict__ Tlo,
              float scale)
{
    __shared__ float xs[64][68];
    __shared__ float as_[16][65];

    const int tid = threadIdx.x;
    const int bm  = blockIdx.x * 64;
    const int r   = tid & 15;
    const int mg  = tid >> 4;

    float a0 = 0.f, a1 = 0.f, a2 = 0.f, a3 = 0.f;

    for (int kt = 0; kt < 1024; kt += 64) {
#pragma unroll
        for (int i = tid; i < 1024; i += 256) {
            int row = i >> 4, c4 = i & 15;
            float4 v = *reinterpret_cast<const float4*>(
                &X[(long long)(bm + row) * 1024 + kt + c4 * 4]);
            *reinterpret_cast<float4*>(&xs[row][c4 * 4]) = v;
        }
#pragma unroll
        for (int i = tid; i < 1024; i += 256) {
            int row = i >> 6, kk = i & 63;
            as_[row][kk] = Amat[row * 1024 + kt + kk];
        }
        __syncthreads();
#pragma unroll 16
        for (int kk = 0; kk < 64; kk++) {
            float a = as_[r][kk];
            a0 = fmaf(xs[mg * 4 + 0][kk], a, a0);
            a1 = fmaf(xs[mg * 4 + 1][kk], a, a1);
            a2 = fmaf(xs[mg * 4 + 2][kk], a, a2);
            a3 = fmaf(xs[mg * 4 + 3][kk], a, a3);
        }
        __syncthreads();
    }
    const __nv_bfloat16 z = __float2bfloat16(0.0f);
#pragma unroll
    for (int q = 0; q < 4; q++) {
        float v = (q == 0 ? a0 : q == 1 ? a1 : q == 2 ? a2 : a3) * scale;
        long long row = bm + mg * 4 + q;
        __nv_bfloat16 h = __float2bfloat16(v);
        __nv_bfloat16 l = __float2bfloat16(v - __bfloat162float(h));
        Thi[row * 32 + r] = h;       Tlo[row * 32 + r] = l;
        Thi[row * 32 + 16 + r] = z;  Tlo[row * 32 + 16 + r] = z;
    }
}

// LoRA intermediate from split-bf16 X (reconstruct hi+lo)
__global__ void __launch_bounds__(256)
lora_t_split(const __nv_bfloat16* __restrict__ Xhi, const __nv_bfloat16* __restrict__ Xlo,
             const float* __restrict__ Amat,
             __nv_bfloat16* __restrict__ Thi, __nv_bfloat16* __restrict__ Tlo,
             float scale)
{
    __shared__ float xs[64][68];
    __shared__ float as_[16][65];

    const int tid = threadIdx.x;
    const int bm  = blockIdx.x * 64;
    const int r   = tid & 15;
    const int mg  = tid >> 4;

    float a0 = 0.f, a1 = 0.f, a2 = 0.f, a3 = 0.f;

    for (int kt = 0; kt < 1024; kt += 64) {
#pragma unroll
        for (int i = tid; i < 1024; i += 256) {
            int row = i >> 4, c4 = i & 15;
            long long base = (long long)(bm + row) * 1024 + kt + c4 * 4;
            uint2 vh = *reinterpret_cast<const uint2*>(Xhi + base);
            uint2 vl = *reinterpret_cast<const uint2*>(Xlo + base);
            __nv_bfloat162 h0 = *reinterpret_cast<__nv_bfloat162*>(&vh.x);
            __nv_bfloat162 h1 = *reinterpret_cast<__nv_bfloat162*>(&vh.y);
            __nv_bfloat162 l0 = *reinterpret_cast<__nv_bfloat162*>(&vl.x);
            __nv_bfloat162 l1 = *reinterpret_cast<__nv_bfloat162*>(&vl.y);
            xs[row][c4*4+0] = __bfloat162float(h0.x) + __bfloat162float(l0.x);
            xs[row][c4*4+1] = __bfloat162float(h0.y) + __bfloat162float(l0.y);
            xs[row][c4*4+2] = __bfloat162float(h1.x) + __bfloat162float(l1.x);
            xs[row][c4*4+3] = __bfloat162float(h1.y) + __bfloat162float(l1.y);
        }
#pragma unroll
        for (int i = tid; i < 1024; i += 256) {
            int row = i >> 6, kk = i & 63;
            as_[row][kk] = Amat[row * 1024 + kt + kk];
        }
        __syncthreads();
#pragma unroll 16
        for (int kk = 0; kk < 64; kk++) {
            float a = as_[r][kk];
            a0 = fmaf(xs[mg * 4 + 0][kk], a, a0);
            a1 = fmaf(xs[mg * 4 + 1][kk], a, a1);
            a2 = fmaf(xs[mg * 4 + 2][kk], a, a2);
            a3 = fmaf(xs[mg * 4 + 3][kk], a, a3);
        }
        __syncthreads();
    }
    const __nv_bfloat16 z = __float2bfloat16(0.0f);
#pragma unroll
    for (int q = 0; q < 4; q++) {
        float v = (q == 0 ? a0 : q == 1 ? a1 : q == 2 ? a2 : a3) * scale;
        long long row = bm + mg * 4 + q;
        __nv_bfloat16 h = __float2bfloat16(v);
        __nv_bfloat16 l = __float2bfloat16(v - __bfloat162float(h));
        Thi[row * 32 + r] = h;       Tlo[row * 32 + r] = l;
        Thi[row * 32 + 16 + r] = z;  Tlo[row * 32 + 16 + r] = z;
    }
}

// ---------------------------------------------------------------------------
// split-bf16 mma.sync GEMM, 3-stage cp.async pipeline.
// C = A*B^T + bias + LoRA (folded as extra K-chunk).
// ---------------------------------------------------------------------------
#define MG_STAGE 32768
#define MG_SMEM  (3 * MG_STAGE)

template<bool SPLIT_OUT>
__global__ void __launch_bounds__(256)
mma_gemm(const __nv_bfloat16* __restrict__ Ahi, const __nv_bfloat16* __restrict__ Alo,
         const __nv_bfloat16* __restrict__ Bhi, const __nv_bfloat16* __restrict__ Blo,
         const __nv_bfloat16* __restrict__ LThi, const __nv_bfloat16* __restrict__ LTlo,
         const __nv_bfloat16* __restrict__ LBhi, const __nv_bfloat16* __restrict__ LBlo,
         float* __restrict__ C, __nv_bfloat16* __restrict__ Chi,
         __nv_bfloat16* __restrict__ Clo,
         int K, int N, const float* __restrict__ bias)
{
    extern __shared__ char smem[];
    const uint32_t sb = smem_u32(smem);
    const int tid  = threadIdx.x;
    const int lane = tid & 31;
    const int warp = tid >> 5;
    const int wm   = warp >> 1;
    const int wn   = warp & 1;
    const int bm = blockIdx.y * 128;
    const int bn = blockIdx.x * 128;

    const int KCH = K >> 5;
    const int NC  = KCH + 1;

    float acc[2][8][4];
#pragma unroll
    for (int m = 0; m < 2; m++)
#pragma unroll
        for (int n = 0; n < 8; n++)
#pragma unroll
            for (int j = 0; j < 4; j++) acc[m][n][j] = 0.0f;

    auto load_chunk = [&](int ch, int st) {
        const bool lora = (ch == KCH);
        const int kt = ch << 5;
#pragma unroll
        for (int i = tid; i < 2048; i += 256) {
            int tile = i >> 9;
            int idx  = i & 511;
            int row  = idx >> 2;
            int c4   = idx & 3;
            const __nv_bfloat16* g;
            long long off;
            if (!lora) {
                g = (tile == 0) ? Ahi : (tile == 1) ? Alo : (tile == 2) ? Bhi : Blo;
                int r0 = (tile < 2) ? bm : bn;
                off = (long long)(r0 + row) * K + kt + c4 * 8;
            } else {
                g = (tile == 0) ? LThi : (tile == 1) ? LTlo : (tile == 2) ? LBhi : LBlo;
                int r0 = (tile < 2) ? bm : bn;
                off = (long long)(r0 + row) * 32 + c4 * 8;
            }
            uint32_t dst = sb + st * MG_STAGE + tile * 8192 + row * 64
                         + ((c4 ^ ((row >> 1) & 3)) << 4);
            cp16(dst, g + off);
        }
        cp_commit();
    };

    load_chunk(0, 0);
    if (NC > 1) load_chunk(1, 1);

    for (int ch = 0; ch < NC; ch++) {
        const int st = ch % 3;
        if (ch + 2 < NC) {
            load_chunk(ch + 2, (ch + 2) % 3);
            asm volatile("cp.async.wait_group 2;" ::: "memory");
        } else if (ch + 1 < NC) {
            asm volatile("cp.async.wait_group 1;" ::: "memory");
        } else {
            asm volatile("cp.async.wait_group 0;" ::: "memory");
        }
        __syncthreads();

        const uint32_t stb = sb + st * MG_STAGE;
#pragma unroll
        for (int kk = 0; kk < 2; kk++) {
            uint32_t ah[2][4], al[2][4];
#pragma unroll
            for (int mf = 0; mf < 2; mf++) {
                int row = wm * 32 + mf * 16 + (lane & 15);
                int c4  = kk * 2 + (lane >> 4);
                uint32_t sw = (uint32_t)((c4 ^ ((row >> 1) & 3)) << 4);
                uint32_t ad = stb + row * 64 + sw;
                ldm_x4(ah[mf][0], ah[mf][1], ah[mf][2], ah[mf][3], ad);
                ldm_x4(al[mf][0], al[mf][1], al[mf][2], al[mf][3], ad + 8192);
            }
            uint32_t bh[8][2], bl[8][2];
#pragma unroll
            for (int p = 0; p < 4; p++) {
                int row = wn * 64 + p * 16 + (lane & 15);
                int c4  = kk * 2 + (lane >> 4);
                uint32_t sw = (uint32_t)((c4 ^ ((row >> 1) & 3)) << 4);
                uint32_t ad = stb + 16384 + row * 64 + sw;
                uint32_t r0, r1, r2, r3;
                ldm_x4(r0, r1, r2, r3, ad);
                bh[2*p][0] = r0; bh[2*p][1] = r2;
                bh[2*p+1][0] = r1; bh[2*p+1][1] = r3;
                ldm_x4(r0, r1, r2, r3, ad + 8192);
                bl[2*p][0] = r0; bl[2*p][1] = r2;
                bl[2*p+1][0] = r1; bl[2*p+1][1] = r3;
            }
#pragma unroll
            for (int mf = 0; mf < 2; mf++)
#pragma unroll
                for (int n = 0; n < 8; n++) {
                    mma_bf16(acc[mf][n], ah[mf], bh[n]);
                    mma_bf16(acc[mf][n], ah[mf], bl[n]);
                    mma_bf16(acc[mf][n], al[mf], bh[n]);
                }
        }
        __syncthreads();
    }

    // ---- epilogue ----
#pragma unroll
    for (int mf = 0; mf < 2; mf++) {
        int r1 = bm + wm * 32 + mf * 16 + (lane >> 2);
#pragma unroll
        for (int n = 0; n < 8; n++) {
            int col = bn + wn * 64 + n * 8 + (lane & 3) * 2;
            float b0 = bias[col], b1 = bias[col + 1];
            float v00 = acc[mf][n][0] + b0, v01 = acc[mf][n][1] + b1;
            float v10 = acc[mf][n][2] + b0, v11 = acc[mf][n][3] + b1;
            if (SPLIT_OUT) {
                __nv_bfloat16 l0, l1;
                __nv_bfloat162 h = pack_split_hi(v00, v01, l0, l1);
                *reinterpret_cast<__nv_bfloat162*>(&Chi[(long long)r1 * N + col]) = h;
                *reinterpret_cast<__nv_bfloat162*>(&Clo[(long long)r1 * N + col]) =
                    __nv_bfloat162(l0, l1);
                h = pack_split_hi(v10, v11, l0, l1);
                *reinterpret_cast<__nv_bfloat162*>(&Chi[(long long)(r1 + 8) * N + col]) = h;
                *reinterpret_cast<__nv_bfloat162*>(&Clo[(long long)(r1 + 8) * N + col]) =
                    __nv_bfloat162(l0, l1);
            } else {
                *reinterpret_cast<float2*>(&C[(long long)r1 * N + col]) =
                    make_float2(v00, v01);
                *reinterpret_cast<float2*>(&C[(long long)(r1 + 8) * N + col]) =
                    make_float2(v10, v11);
            }
        }
    }
}

// ---------------------------------------------------------------------------
// Fused attention with causal skip; outputs split bf16 Y.
// grid = (T/64, B*H), 256 threads.
// ---------------------------------------------------------------------------
#define FA_V_H   81920
#define FA_V_L   114688
#define FA_REDM  147456
#define FA_REDS  148480
#define FA_SMEM  149504

__global__ void __launch_bounds__(256)
fa_kernel(const __nv_bfloat16* __restrict__ Qh, const __nv_bfloat16* __restrict__ Ql,
          const __nv_bfloat16* __restrict__ KVh, const __nv_bfloat16* __restrict__ KVl,
          __nv_bfloat16* __restrict__ Yh, __nv_bfloat16* __restrict__ Yl)
{
    extern __shared__ char smem[];
    const uint32_t sb = smem_u32(smem);
    const int tid  = threadIdx.x;
    const int lane = tid & 31;
    const int warp = tid >> 5;
    const int bh = blockIdx.y;
    const int b = bh >> 4, h = bh & 15;
    const int t0 = blockIdx.x * 64;
    const bool need_mask = (t0 < Slen);
    const int tmax = t0 + 63;
    const int smax = need_mask ? (t0 + 64) : Slen;

    // ---- async loads ----
    {
        const long long qbase = ((long long)(b * 1024 + t0)) * 1024 + h * 64;
#pragma unroll
        for (int i = tid; i < 512; i += 256) {
            int row = i >> 3, c = i & 7;
            uint32_t sw = (uint32_t)((c ^ (row & 7)) << 4);
            cp16(sb + row * 128 + sw,        Qh + qbase + (long long)row * 1024 + c * 8);
            cp16(sb + 8192 + row * 128 + sw, Ql + qbase + (long long)row * 1024 + c * 8);
        }
        const long long kbase = ((long long)(b * 256)) * 2048 + h * 64;
        const long long vbase = kbase + 1024;
#pragma unroll
        for (int i = tid; i < 2048; i += 256) {
            int row = i >> 3, c = i & 7;
            if (row < smax) {
                uint32_t sw = (uint32_t)((c ^ (row & 7)) << 4);
                long long go = (long long)row * 2048 + c * 8;
                cp16(sb + 16384  + row * 128 + sw, KVh + kbase + go);
                cp16(sb + 49152  + row * 128 + sw, KVl + kbase + go);
                cp16(sb + FA_V_H + row * 128 + sw, KVh + vbase + go);
                cp16(sb + FA_V_L + row * 128 + sw, KVl + vbase + go);
            }
        }
        cp_commit();
        asm volatile("cp.async.wait_group 0;" ::: "memory");
    }
    __syncthreads();

    const int rq = lane >> 2, cq = lane & 3;

    // ---- phase 1: S = Q K^T (64x256x64), warp tile 32x64 ----
    const int wm = warp >> 2;
    const int wn = warp & 3;
    float acc[2][8][4];
#pragma unroll
    for (int m = 0; m < 2; m++)
#pragma unroll
        for (int n = 0; n < 8; n++)
#pragma unroll
            for (int j = 0; j < 4; j++) acc[m][n][j] = 0.0f;

#pragma unroll
    for (int ks = 0; ks < 4; ks++) {
        uint32_t ah[2][4], al[2][4];
#pragma unroll
        for (int mf = 0; mf < 2; mf++) {
            int row = wm * 32 + mf * 16 + (lane & 15);
            int ch  = ks * 2 + (lane >> 4);
            uint32_t ad = sb + row * 128 + (uint32_t)((ch ^ (row & 7)) << 4);
            ldm_x4(ah[mf][0], ah[mf][1], ah[mf][2], ah[mf][3], ad);
            ldm_x4(al[mf][0], al[mf][1], al[mf][2], al[mf][3], ad + 8192);
        }
        uint32_t bh_[8][2], bl_[8][2];
#pragma unroll
        for (int p = 0; p < 4; p++) {
            if (need_mask && (wn * 64 + p * 16) > tmax) continue;
            int row = wn * 64 + p * 16 + (lane & 15);
            int ch  = ks * 2 + (lane >> 4);
            uint32_t ad = sb + 16384 + row * 128 + (uint32_t)((ch ^ (row & 7)) << 4);
            uint32_t r0, r1, r2, r3;
            ldm_x4(r0, r1, r2, r3, ad);
            bh_[2*p][0] = r0; bh_[2*p][1] = r2;
            bh_[2*p+1][0] = r1; bh_[2*p+1][1] = r3;
            ldm_x4(r0, r1, r2, r3, ad + 32768);
            bl_[2*p][0] = r0; bl_[2*p][1] = r2;
            bl_[2*p+1][0] = r1; bl_[2*p+1][1] = r3;
        }
#pragma unroll
        for (int mf = 0; mf < 2; mf++)
#pragma unroll
            for (int n = 0; n < 8; n++) {
                if (need_mask && (wn * 64 + n * 8) > tmax) continue;
                mma_bf16(acc[mf][n], ah[mf], bh_[n]);
                mma_bf16(acc[mf][n], ah[mf], bl_[n]);
                mma_bf16(acc[mf][n], al[mf], bh_[n]);
            }
    }

    // ---- softmax ----
    float* red_max = reinterpret_cast<float*>(smem + FA_REDM);
    float* red_sum = reinterpret_cast<float*>(smem + FA_REDS);

#pragma unroll
    for (int mf = 0; mf < 2; mf++)
#pragma unroll
        for (int sub = 0; sub < 2; sub++) {
            int rl = wm * 32 + mf * 16 + sub * 8 + rq;
            int trow = t0 + rl;
            float m = -1e30f;
#pragma unroll
            for (int nf = 0; nf < 8; nf++) {
                int col = wn * 64 + nf * 8 + cq * 2;
                float v0 = acc[mf][nf][sub*2]     * 0.125f;
                float v1 = acc[mf][nf][sub*2 + 1] * 0.125f;
                if (need_mask) {
                    if (col     > trow) v0 = -1e30f;
                    if (col + 1 > trow) v1 = -1e30f;
                }
                acc[mf][nf][sub*2]     = v0;
                acc[mf][nf][sub*2 + 1] = v1;
                m = fmaxf(m, fmaxf(v0, v1));
            }
            m = fmaxf(m, __shfl_xor_sync(0xffffffffu, m, 1));
            m = fmaxf(m, __shfl_xor_sync(0xffffffffu, m, 2));
            if (cq == 0) red_max[wn * 64 + rl] = m;
        }
    __syncthreads();

#pragma unroll
    for (int mf = 0; mf < 2; mf++)
#pragma unroll
        for (int sub = 0; sub < 2; sub++) {
            int rl = wm * 32 + mf * 16 + sub * 8 + rq;
            float M = fmaxf(fmaxf(red_max[rl], red_max[64 + rl]),
                            fmaxf(red_max[128 + rl], red_max[192 + rl]));
            float s = 0.0f;
#pragma unroll
            for (int nf = 0; nf < 8; nf++) {
                float e0 = __expf(acc[mf][nf][sub*2]     - M);
                float e1 = __expf(acc[mf][nf][sub*2 + 1] - M);
                acc[mf][nf][sub*2]     = e0;
                acc[mf][nf][sub*2 + 1] = e1;
                s += e0 + e1;
            }
            s += __shfl_xor_sync(0xffffffffu, s, 1);
            s += __shfl_xor_sync(0xffffffffu, s, 2);
            if (cq == 0) red_sum[wn * 64 + rl] = s;
        }
    __syncthreads();

    // ---- store P split bf16 ----
#pragma unroll
    for (int mf = 0; mf < 2; mf++)
#pragma unroll
        for (int sub = 0; sub < 2; sub++) {
            int rl = wm * 32 + mf * 16 + sub * 8 + rq;
#pragma unroll
            for (int nf = 0; nf < 8; nf++) {
                int col = wn * 64 + nf * 8 + cq * 2;
                __nv_bfloat16 l0, l1;
                __nv_bfloat162 hh = pack_split_hi(acc[mf][nf][sub*2],
                                                  acc[mf][nf][sub*2 + 1], l0, l1);
                int chnk = col >> 3;
                uint32_t off = (uint32_t)(rl * 512 + ((chnk ^ (rl & 7)) << 4) + (col & 7) * 2);
                *reinterpret_cast<__nv_bfloat162*>(smem + off) = hh;
                *reinterpret_cast<__nv_bfloat162*>(smem + 32768 + off) = __nv_bfloat162(l0, l1);
            }
        }
    __syncthreads();

    // ---- phase 2: Y = P V, K bounded by causal structure ----
    const int wm2 = warp >> 2;
    const int wn2 = warp & 3;
    const int nks = need_mask ? ((tmax >> 4) + 1) : 16;
    float acc2[2][2][4];
#pragma unroll
    for (int m = 0; m < 2; m++)
#pragma unroll
        for (int n = 0; n < 2; n++)
#pragma unroll
            for (int j = 0; j < 4; j++) acc2[m][n][j] = 0.0f;

    for (int ks = 0; ks < nks; ks++) {
        uint32_t ph[2][4], pl[2][4];
#pragma unroll
        for (int mf = 0; mf < 2; mf++) {
            int row = wm2 * 32 + mf * 16 + (lane & 15);
            int ch  = ks * 2 + (lane >> 4);
            uint32_t ad = sb + row * 512 + (uint32_t)((ch ^ (row & 7)) << 4);
            ldm_x4(ph[mf][0], ph[mf][1], ph[mf][2], ph[mf][3], ad);
            ldm_x4(pl[mf][0], pl[mf][1], pl[mf][2], pl[mf][3], ad + 32768);
        }
        uint32_t vh_[2][2], vl_[2][2];
        {
            int g = lane >> 3;
            int srow = ks * 16 + (g & 1) * 8 + (lane & 7);
            int dch  = wn2 * 2 + (g >> 1);
            uint32_t ad = sb + FA_V_H + srow * 128 + (uint32_t)((dch ^ (srow & 7)) << 4);
            uint32_t r0, r1, r2, r3;
            ldm_x4t(r0, r1, r2, r3, ad);
            vh_[0][0] = r0; vh_[0][1] = r1; vh_[1][0] = r2; vh_[1][1] = r3;
            ldm_x4t(r0, r1, r2, r3, ad + 32768);
            vl_[0][0] = r0; vl_[0][1] = r1; vl_[1][0] = r2; vl_[1][1] = r3;
        }
#pragma unroll
        for (int mf = 0; mf < 2; mf++)
#pragma unroll
            for (int nf = 0; nf < 2; nf++) {
                mma_bf16(acc2[mf][nf], ph[mf], vh_[nf]);
                mma_bf16(acc2[mf][nf], ph[mf], vl_[nf]);
                mma_bf16(acc2[mf][nf], pl[mf], vh_[nf]);
            }
    }

    // ---- epilogue: normalize, split-bf16 store ----
#pragma unroll
    for (int mf = 0; mf < 2; mf++)
#pragma unroll
        for (int sub = 0; sub < 2; sub++) {
            int rl = wm2 * 32 + mf * 16 + sub * 8 + rq;
            float inv = 1.0f / (red_sum[rl] + red_sum[64 + rl] +
                                red_sum[128 + rl] + red_sum[192 + rl]);
            long long yo = ((long long)(b * 1024 + t0 + rl)) * 1024 + h * 64;
#pragma unroll
            for (int nf = 0; nf < 2; nf++) {
                int col = wn2 * 16 + nf * 8 + cq * 2;
                float v0 = acc2[mf][nf][sub*2]     * inv;
                float v1 = acc2[mf][nf][sub*2 + 1] * inv;
                __nv_bfloat16 l0, l1;
                __nv_bfloat162 hh = pack_split_hi(v0, v1, l0, l1);
                *reinterpret_cast<__nv_bfloat162*>(&Yh[yo + col]) = hh;
                *reinterpret_cast<__nv_bfloat162*>(&Yl[yo + col]) = __nv_bfloat162(l0, l1);
            }
        }
}

// ---------------------------------------------------------------------------
// Launch
// ---------------------------------------------------------------------------
extern "C" void kernel_launch(void* const* d_in, const int* in_sizes, int n_in,
                              void* d_out, int out_size)
{
    const float* x  = (const float*)d_in[0];
    const float* ft = (const float*)d_in[1];
    const float* Wq = (const float*)d_in[2];
    const float* bq = (const float*)d_in[3];
    const float* Aq = (const float*)d_in[4];
    const float* Bq = (const float*)d_in[5];
    const float* Wf = (const float*)d_in[6];
    const float* bfv= (const float*)d_in[7];
    const float* Af = (const float*)d_in[8];
    const float* Bf = (const float*)d_in[9];
    const float* Wp = (const float*)d_in[10];
    const float* bp = (const float*)d_in[11];
    const float* Ap = (const float*)d_in[12];
    const float* Bp = (const float*)d_in[13];
    float* out = (float*)d_out;

    __nv_bfloat16 *xhi, *xlo, *fhi, *flo, *yhi, *ylo;
    __nv_bfloat16 *wqhi, *wqlo, *wfhi, *wflo, *wphi, *wplo;
    __nv_bfloat16 *qh, *ql, *kvh, *kvl;
    __nv_bfloat16 *tqh, *tql, *tfh, *tfl, *tph, *tpl;
    __nv_bfloat16 *bqh, *bql, *bfh, *bfl, *bph, *bpl;
    cudaGetSymbolAddress((void**)&xhi, g_xhi);  cudaGetSymbolAddress((void**)&xlo, g_xlo);
    cudaGetSymbolAddress((void**)&fhi, g_fhi);  cudaGetSymbolAddress((void**)&flo, g_flo);
    cudaGetSymbolAddress((void**)&yhi, g_yhi);  cudaGetSymbolAddress((void**)&ylo, g_ylo);
    cudaGetSymbolAddress((void**)&wqhi, g_wqhi); cudaGetSymbolAddress((void**)&wqlo, g_wqlo);
    cudaGetSymbolAddress((void**)&wfhi, g_wfhi); cudaGetSymbolAddress((void**)&wflo, g_wflo);
    cudaGetSymbolAddress((void**)&wphi, g_wphi); cudaGetSymbolAddress((void**)&wplo, g_wplo);
    cudaGetSymbolAddress((void**)&qh, g_qh);    cudaGetSymbolAddress((void**)&ql, g_ql);
    cudaGetSymbolAddress((void**)&kvh, g_kvh);  cudaGetSymbolAddress((void**)&kvl, g_kvl);
    cudaGetSymbolAddress((void**)&tqh, g_tqh);  cudaGetSymbolAddress((void**)&tql, g_tql);
    cudaGetSymbolAddress((void**)&tfh, g_tfh);  cudaGetSymbolAddress((void**)&tfl, g_tfl);
    cudaGetSymbolAddress((void**)&tph, g_tph);  cudaGetSymbolAddress((void**)&tpl, g_tpl);
    cudaGetSymbolAddress((void**)&bqh, g_bqh);  cudaGetSymbolAddress((void**)&bql, g_bql);
    cudaGetSymbolAddress((void**)&bfh, g_bfh);  cudaGetSymbolAddress((void**)&bfl, g_bfl);
    cudaGetSymbolAddress((void**)&bph, g_bph);  cudaGetSymbolAddress((void**)&bpl, g_bpl);

    cudaFuncSetAttribute(mma_gemm<false>, cudaFuncAttributeMaxDynamicSharedMemorySize, MG_SMEM);
    cudaFuncSetAttribute(mma_gemm<true>,  cudaFuncAttributeMaxDynamicSharedMemorySize, MG_SMEM);
    cudaFuncSetAttribute(fa_kernel, cudaFuncAttributeMaxDynamicSharedMemorySize, FA_SMEM);

    const float SC = 1.0f / 16.0f;

    // merged splits
    split_multi<<<(SEG4 + 255)/256, 256>>>(
        (const float4*)x, (const float4*)Wq, (const float4*)ft,
        (const float4*)Wf, (const float4*)Wp,
        (__nv_bfloat162*)xhi,  (__nv_bfloat162*)xlo,
        (__nv_bfloat162*)wqhi, (__nv_bfloat162*)wqlo,
        (__nv_bfloat162*)fhi,  (__nv_bfloat162*)flo,
        (__nv_bfloat162*)wfhi, (__nv_bfloat162*)wflo,
        (__nv_bfloat162*)wphi, (__nv_bfloat162*)wplo);

    // LoRA factors
    lora_t_kernel<<<128, 256>>>(x, Aq, tqh, tql, SC);
    lora_t_kernel<<<32, 256>>>(ft, Af, tfh, tfl, SC);
    splitpad_multi<<<16, 256>>>(Bq, Bf, Bp, bqh, bql, bfh, bfl, bph, bpl);

    // Q projection -> split bf16
    mma_gemm<true><<<dim3(8, 64), 256, MG_SMEM>>>(xhi, xlo, wqhi, wqlo,
        tqh, tql, bqh, bql, nullptr, qh, ql, 1024, 1024, bq);

    // KV projection -> split bf16
    mma_gemm<true><<<dim3(16, 16), 256, MG_SMEM>>>(fhi, flo, wfhi, wflo,
        tfh, tfl, bfh, bfl, nullptr, kvh, kvl, 1024, 2048, bfv);

    // fused attention -> split bf16 Y
    fa_kernel<<<dim3(16, 128), 256, FA_SMEM>>>(qh, ql, kvh, kvl, yhi, ylo);

    // LoRA for P from split Y
    lora_t_split<<<128, 256>>>(yhi, ylo, Ap, tph, tpl, SC);

    // out = y @ Wp^T + bp + lora  (fp32 out)
    mma_gemm<false><<<dim3(8, 64), 256, MG_SMEM>>>(yhi, ylo, wphi, wplo,
        tph, tpl, bph, bpl, out, nullptr, nullptr, 1024, 1024, bp);
}

// round 6
// speedup vs baseline: 2.5937x; 1.0538x over previous
#include <cuda_runtime.h>
#include <cuda_bf16.h>
#include <math.h>
#include <stdint.h>

// ---------------------------------------------------------------------------
// CrossAttention with LoRA — round 6
// persistent-attention CTAs, fixed splitpad, merged lora prep
// B=8, T=1024, S=256, C=1024, H=16, D=64, R=16, SCALING=1/16
// ---------------------------------------------------------------------------

#define Bsz   8
#define Tlen  1024
#define Slen  256
#define Cdim  1024

__device__ __align__(16) __nv_bfloat16 g_xhi[Bsz*Tlen*Cdim], g_xlo[Bsz*Tlen*Cdim];
__device__ __align__(16) __nv_bfloat16 g_fhi[Bsz*Slen*Cdim], g_flo[Bsz*Slen*Cdim];
__device__ __align__(16) __nv_bfloat16 g_yhi[Bsz*Tlen*Cdim], g_ylo[Bsz*Tlen*Cdim];
__device__ __align__(16) __nv_bfloat16 g_wqhi[Cdim*Cdim],   g_wqlo[Cdim*Cdim];
__device__ __align__(16) __nv_bfloat16 g_wfhi[2*Cdim*Cdim], g_wflo[2*Cdim*Cdim];
__device__ __align__(16) __nv_bfloat16 g_wphi[Cdim*Cdim],   g_wplo[Cdim*Cdim];

__device__ __align__(16) __nv_bfloat16 g_qh[Bsz*Tlen*Cdim],     g_ql[Bsz*Tlen*Cdim];
__device__ __align__(16) __nv_bfloat16 g_kvh[Bsz*Slen*2*Cdim],  g_kvl[Bsz*Slen*2*Cdim];

__device__ __align__(16) __nv_bfloat16 g_tqh[Bsz*Tlen*32], g_tql[Bsz*Tlen*32];
__device__ __align__(16) __nv_bfloat16 g_tfh[Bsz*Slen*32], g_tfl[Bsz*Slen*32];
__device__ __align__(16) __nv_bfloat16 g_tph[Bsz*Tlen*32], g_tpl[Bsz*Tlen*32];
__device__ __align__(16) __nv_bfloat16 g_bqh[Cdim*32],   g_bql[Cdim*32];
__device__ __align__(16) __nv_bfloat16 g_bfh[2*Cdim*32], g_bfl[2*Cdim*32];
__device__ __align__(16) __nv_bfloat16 g_bph[Cdim*32],   g_bpl[Cdim*32];

// ---------------------------------------------------------------------------
__device__ __forceinline__ uint32_t smem_u32(const void* p) {
    uint32_t a;
    asm("{ .reg .u64 t; cvta.to.shared.u64 t, %1; cvt.u32.u64 %0, t; }" : "=r"(a) : "l"(p));
    return a;
}
__device__ __forceinline__ void cp16(uint32_t dst, const void* src) {
    asm volatile("cp.async.cg.shared.global [%0], [%1], 16;" :: "r"(dst), "l"(src));
}
__device__ __forceinline__ void cp_commit() {
    asm volatile("cp.async.commit_group;" ::: "memory");
}
__device__ __forceinline__ void ldm_x4(uint32_t& r0, uint32_t& r1, uint32_t& r2, uint32_t& r3,
                                       uint32_t addr) {
    asm volatile("ldmatrix.sync.aligned.m8n8.x4.shared.b16 {%0,%1,%2,%3}, [%4];"
                 : "=r"(r0), "=r"(r1), "=r"(r2), "=r"(r3) : "r"(addr));
}
__device__ __forceinline__ void ldm_x4t(uint32_t& r0, uint32_t& r1, uint32_t& r2, uint32_t& r3,
                                        uint32_t addr) {
    asm volatile("ldmatrix.sync.aligned.m8n8.x4.trans.shared.b16 {%0,%1,%2,%3}, [%4];"
                 : "=r"(r0), "=r"(r1), "=r"(r2), "=r"(r3) : "r"(addr));
}
__device__ __forceinline__ void mma_bf16(float* c, const uint32_t* a, const uint32_t* b) {
    asm volatile(
        "mma.sync.aligned.m16n8k16.row.col.f32.bf16.bf16.f32 "
        "{%0,%1,%2,%3}, {%4,%5,%6,%7}, {%8,%9}, {%0,%1,%2,%3};"
        : "+f"(c[0]), "+f"(c[1]), "+f"(c[2]), "+f"(c[3])
        : "r"(a[0]), "r"(a[1]), "r"(a[2]), "r"(a[3]), "r"(b[0]), "r"(b[1]));
}
__device__ __forceinline__ __nv_bfloat162 pack_split_hi(float v0, float v1,
                                                        __nv_bfloat16& l0, __nv_bfloat16& l1) {
    __nv_bfloat16 h0 = __float2bfloat16(v0);
    __nv_bfloat16 h1 = __float2bfloat16(v1);
    l0 = __float2bfloat16(v0 - __bfloat162float(h0));
    l1 = __float2bfloat16(v1 - __bfloat162float(h1));
    return __nv_bfloat162(h0, h1);
}

// ---------------------------------------------------------------------------
// merged fp32 -> (hi, lo) split over 5 tensors
// ---------------------------------------------------------------------------
#define SEG0 (Bsz*Tlen*Cdim/4)
#define SEG1 (SEG0 + Cdim*Cdim/4)
#define SEG2 (SEG1 + Bsz*Slen*Cdim/4)
#define SEG3 (SEG2 + 2*Cdim*Cdim/4)
#define SEG4 (SEG3 + Cdim*Cdim/4)

__global__ void __launch_bounds__(256)
split_multi(const float4* __restrict__ x,  const float4* __restrict__ Wq,
            const float4* __restrict__ ft, const float4* __restrict__ Wf,
            const float4* __restrict__ Wp,
            __nv_bfloat162* __restrict__ xhi,  __nv_bfloat162* __restrict__ xlo,
            __nv_bfloat162* __restrict__ wqhi, __nv_bfloat162* __restrict__ wqlo,
            __nv_bfloat162* __restrict__ fhi,  __nv_bfloat162* __restrict__ flo,
            __nv_bfloat162* __restrict__ wfhi, __nv_bfloat162* __restrict__ wflo,
            __nv_bfloat162* __restrict__ wphi, __nv_bfloat162* __restrict__ wplo)
{
    int gi = blockIdx.x * 256 + threadIdx.x;
    if (gi >= SEG4) return;
    const float4* in; __nv_bfloat162* hi; __nv_bfloat162* lo; int i;
    if (gi < SEG0)      { in = x;  hi = xhi;  lo = xlo;  i = gi; }
    else if (gi < SEG1) { in = Wq; hi = wqhi; lo = wqlo; i = gi - SEG0; }
    else if (gi < SEG2) { in = ft; hi = fhi;  lo = flo;  i = gi - SEG1; }
    else if (gi < SEG3) { in = Wf; hi = wfhi; lo = wflo; i = gi - SEG2; }
    else                { in = Wp; hi = wphi; lo = wplo; i = gi - SEG3; }
    float4 v = in[i];
    __nv_bfloat16 l0, l1, l2, l3;
    __nv_bfloat162 h01 = pack_split_hi(v.x, v.y, l0, l1);
    __nv_bfloat162 h23 = pack_split_hi(v.z, v.w, l2, l3);
    hi[2*i]   = h01;
    hi[2*i+1] = h23;
    lo[2*i]   = __nv_bfloat162(l0, l1);
    lo[2*i+1] = __nv_bfloat162(l2, l3);
}

// splitpad: one thread per (row, 2 cols); 4096 rows x 8 pairs = 32768 threads
__global__ void __launch_bounds__(256)
splitpad_multi(const float* __restrict__ Bq, const float* __restrict__ Bf,
               const float* __restrict__ Bp,
               __nv_bfloat16* __restrict__ qh, __nv_bfloat16* __restrict__ ql,
               __nv_bfloat16* __restrict__ fh, __nv_bfloat16* __restrict__ fl,
               __nv_bfloat16* __restrict__ ph, __nv_bfloat16* __restrict__ pl)
{
    int g = blockIdx.x * 256 + threadIdx.x;
    if (g >= 32768) return;
    int row = g >> 3;
    int j2  = (g & 7) * 2;
    const float* B; __nv_bfloat16* hi; __nv_bfloat16* lo;
    if (row < 1024)      { B = Bq; hi = qh; lo = ql; }
    else if (row < 3072) { B = Bf; hi = fh; lo = fl; row -= 1024; }
    else                 { B = Bp; hi = ph; lo = pl; row -= 3072; }
    float2 v = *reinterpret_cast<const float2*>(B + row * 16 + j2);
    __nv_bfloat16 l0, l1;
    __nv_bfloat162 h = pack_split_hi(v.x, v.y, l0, l1);
    *reinterpret_cast<__nv_bfloat162*>(hi + row * 32 + j2) = h;
    *reinterpret_cast<__nv_bfloat162*>(lo + row * 32 + j2) = __nv_bfloat162(l0, l1);
    __nv_bfloat162 z2(__float2bfloat16(0.0f), __float2bfloat16(0.0f));
    *reinterpret_cast<__nv_bfloat162*>(hi + row * 32 + 16 + j2) = z2;
    *reinterpret_cast<__nv_bfloat162*>(lo + row * 32 + 16 + j2) = z2;
}

// ---------------------------------------------------------------------------
// merged LoRA intermediates for q (x/Aq, 128 blocks) and f (ft/Af, 32 blocks)
// ---------------------------------------------------------------------------
__global__ void __launch_bounds__(256)
lora_t_merged(const float* __restrict__ x,  const float* __restrict__ Aq,
              const float* __restrict__ ft, const float* __restrict__ Af,
              __nv_bfloat16* __restrict__ tqh, __nv_bfloat16* __restrict__ tql,
              __nv_bfloat16* __restrict__ tfh, __nv_bfloat16* __restrict__ tfl,
              float scale)
{
    __shared__ float xs[64][68];
    __shared__ float as_[16][65];

    const int tid = threadIdx.x;
    const float* X; const float* Am; __nv_bfloat16 *Th, *Tl; int bm;
    if (blockIdx.x < 128) { X = x;  Am = Aq; Th = tqh; Tl = tql; bm = blockIdx.x * 64; }
    else                  { X = ft; Am = Af; Th = tfh; Tl = tfl; bm = (blockIdx.x - 128) * 64; }

    const int r  = tid & 15;
    const int mg = tid >> 4;
    float a0 = 0.f, a1 = 0.f, a2 = 0.f, a3 = 0.f;

    for (int kt = 0; kt < 1024; kt += 64) {
#pragma unroll
        for (int i = tid; i < 1024; i += 256) {
            int row = i >> 4, c4 = i & 15;
            float4 v = *reinterpret_cast<const float4*>(
                &X[(long long)(bm + row) * 1024 + kt + c4 * 4]);
            *reinterpret_cast<float4*>(&xs[row][c4 * 4]) = v;
        }
#pragma unroll
        for (int i = tid; i < 1024; i += 256) {
            int row = i >> 6, kk = i & 63;
            as_[row][kk] = Am[row * 1024 + kt + kk];
        }
        __syncthreads();
#pragma unroll 16
        for (int kk = 0; kk < 64; kk++) {
            float a = as_[r][kk];
            a0 = fmaf(xs[mg * 4 + 0][kk], a, a0);
            a1 = fmaf(xs[mg * 4 + 1][kk], a, a1);
            a2 = fmaf(xs[mg * 4 + 2][kk], a, a2);
            a3 = fmaf(xs[mg * 4 + 3][kk], a, a3);
        }
        __syncthreads();
    }
    const __nv_bfloat16 z = __float2bfloat16(0.0f);
#pragma unroll
    for (int q = 0; q < 4; q++) {
        float v = (q == 0 ? a0 : q == 1 ? a1 : q == 2 ? a2 : a3) * scale;
        long long row = bm + mg * 4 + q;
        __nv_bfloat16 h = __float2bfloat16(v);
        __nv_bfloat16 l = __float2bfloat16(v - __bfloat162float(h));
        Th[row * 32 + r] = h;       Tl[row * 32 + r] = l;
        Th[row * 32 + 16 + r] = z;  Tl[row * 32 + 16 + r] = z;
    }
}

// LoRA intermediate from split-bf16 X
__global__ void __launch_bounds__(256)
lora_t_split(const __nv_bfloat16* __restrict__ Xhi, const __nv_bfloat16* __restrict__ Xlo,
             const float* __restrict__ Amat,
             __nv_bfloat16* __restrict__ Thi, __nv_bfloat16* __restrict__ Tlo,
             float scale)
{
    __shared__ float xs[64][68];
    __shared__ float as_[16][65];

    const int tid = threadIdx.x;
    const int bm  = blockIdx.x * 64;
    const int r   = tid & 15;
    const int mg  = tid >> 4;

    float a0 = 0.f, a1 = 0.f, a2 = 0.f, a3 = 0.f;

    for (int kt = 0; kt < 1024; kt += 64) {
#pragma unroll
        for (int i = tid; i < 1024; i += 256) {
            int row = i >> 4, c4 = i & 15;
            long long base = (long long)(bm + row) * 1024 + kt + c4 * 4;
            uint2 vh = *reinterpret_cast<const uint2*>(Xhi + base);
            uint2 vl = *reinterpret_cast<const uint2*>(Xlo + base);
            __nv_bfloat162 h0 = *reinterpret_cast<__nv_bfloat162*>(&vh.x);
            __nv_bfloat162 h1 = *reinterpret_cast<__nv_bfloat162*>(&vh.y);
            __nv_bfloat162 l0 = *reinterpret_cast<__nv_bfloat162*>(&vl.x);
            __nv_bfloat162 l1 = *reinterpret_cast<__nv_bfloat162*>(&vl.y);
            xs[row][c4*4+0] = __bfloat162float(h0.x) + __bfloat162float(l0.x);
            xs[row][c4*4+1] = __bfloat162float(h0.y) + __bfloat162float(l0.y);
            xs[row][c4*4+2] = __bfloat162float(h1.x) + __bfloat162float(l1.x);
            xs[row][c4*4+3] = __bfloat162float(h1.y) + __bfloat162float(l1.y);
        }
#pragma unroll
        for (int i = tid; i < 1024; i += 256) {
            int row = i >> 6, kk = i & 63;
            as_[row][kk] = Amat[row * 1024 + kt + kk];
        }
        __syncthreads();
#pragma unroll 16
        for (int kk = 0; kk < 64; kk++) {
            float a = as_[r][kk];
            a0 = fmaf(xs[mg * 4 + 0][kk], a, a0);
            a1 = fmaf(xs[mg * 4 + 1][kk], a, a1);
            a2 = fmaf(xs[mg * 4 + 2][kk], a, a2);
            a3 = fmaf(xs[mg * 4 + 3][kk], a, a3);
        }
        __syncthreads();
    }
    const __nv_bfloat16 z = __float2bfloat16(0.0f);
#pragma unroll
    for (int q = 0; q < 4; q++) {
        float v = (q == 0 ? a0 : q == 1 ? a1 : q == 2 ? a2 : a3) * scale;
        long long row = bm + mg * 4 + q;
        __nv_bfloat16 h = __float2bfloat16(v);
        __nv_bfloat16 l = __float2bfloat16(v - __bfloat162float(h));
        Thi[row * 32 + r] = h;       Tlo[row * 32 + r] = l;
        Thi[row * 32 + 16 + r] = z;  Tlo[row * 32 + 16 + r] = z;
    }
}

// ---------------------------------------------------------------------------
// split-bf16 mma.sync GEMM, 3-stage cp.async pipeline (unchanged from R5)
// ---------------------------------------------------------------------------
#define MG_STAGE 32768
#define MG_SMEM  (3 * MG_STAGE)

template<bool SPLIT_OUT>
__global__ void __launch_bounds__(256)
mma_gemm(const __nv_bfloat16* __restrict__ Ahi, const __nv_bfloat16* __restrict__ Alo,
         const __nv_bfloat16* __restrict__ Bhi, const __nv_bfloat16* __restrict__ Blo,
         const __nv_bfloat16* __restrict__ LThi, const __nv_bfloat16* __restrict__ LTlo,
         const __nv_bfloat16* __restrict__ LBhi, const __nv_bfloat16* __restrict__ LBlo,
         float* __restrict__ C, __nv_bfloat16* __restrict__ Chi,
         __nv_bfloat16* __restrict__ Clo,
         int K, int N, const float* __restrict__ bias)
{
    extern __shared__ char smem[];
    const uint32_t sb = smem_u32(smem);
    const int tid  = threadIdx.x;
    const int lane = tid & 31;
    const int warp = tid >> 5;
    const int wm   = warp >> 1;
    const int wn   = warp & 1;
    const int bm = blockIdx.y * 128;
    const int bn = blockIdx.x * 128;

    const int KCH = K >> 5;
    const int NC  = KCH + 1;

    float acc[2][8][4];
#pragma unroll
    for (int m = 0; m < 2; m++)
#pragma unroll
        for (int n = 0; n < 8; n++)
#pragma unroll
            for (int j = 0; j < 4; j++) acc[m][n][j] = 0.0f;

    auto load_chunk = [&](int ch, int st) {
        const bool lora = (ch == KCH);
        const int kt = ch << 5;
#pragma unroll
        for (int i = tid; i < 2048; i += 256) {
            int tile = i >> 9;
            int idx  = i & 511;
            int row  = idx >> 2;
            int c4   = idx & 3;
            const __nv_bfloat16* g;
            long long off;
            if (!lora) {
                g = (tile == 0) ? Ahi : (tile == 1) ? Alo : (tile == 2) ? Bhi : Blo;
                int r0 = (tile < 2) ? bm : bn;
                off = (long long)(r0 + row) * K + kt + c4 * 8;
            } else {
                g = (tile == 0) ? LThi : (tile == 1) ? LTlo : (tile == 2) ? LBhi : LBlo;
                int r0 = (tile < 2) ? bm : bn;
                off = (long long)(r0 + row) * 32 + c4 * 8;
            }
            uint32_t dst = sb + st * MG_STAGE + tile * 8192 + row * 64
                         + ((c4 ^ ((row >> 1) & 3)) << 4);
            cp16(dst, g + off);
        }
        cp_commit();
    };

    load_chunk(0, 0);
    if (NC > 1) load_chunk(1, 1);

    for (int ch = 0; ch < NC; ch++) {
        const int st = ch % 3;
        if (ch + 2 < NC) {
            load_chunk(ch + 2, (ch + 2) % 3);
            asm volatile("cp.async.wait_group 2;" ::: "memory");
        } else if (ch + 1 < NC) {
            asm volatile("cp.async.wait_group 1;" ::: "memory");
        } else {
            asm volatile("cp.async.wait_group 0;" ::: "memory");
        }
        __syncthreads();

        const uint32_t stb = sb + st * MG_STAGE;
#pragma unroll
        for (int kk = 0; kk < 2; kk++) {
            uint32_t ah[2][4], al[2][4];
#pragma unroll
            for (int mf = 0; mf < 2; mf++) {
                int row = wm * 32 + mf * 16 + (lane & 15);
                int c4  = kk * 2 + (lane >> 4);
                uint32_t sw = (uint32_t)((c4 ^ ((row >> 1) & 3)) << 4);
                uint32_t ad = stb + row * 64 + sw;
                ldm_x4(ah[mf][0], ah[mf][1], ah[mf][2], ah[mf][3], ad);
                ldm_x4(al[mf][0], al[mf][1], al[mf][2], al[mf][3], ad + 8192);
            }
            uint32_t bh[8][2], bl[8][2];
#pragma unroll
            for (int p = 0; p < 4; p++) {
                int row = wn * 64 + p * 16 + (lane & 15);
                int c4  = kk * 2 + (lane >> 4);
                uint32_t sw = (uint32_t)((c4 ^ ((row >> 1) & 3)) << 4);
                uint32_t ad = stb + 16384 + row * 64 + sw;
                uint32_t r0, r1, r2, r3;
                ldm_x4(r0, r1, r2, r3, ad);
                bh[2*p][0] = r0; bh[2*p][1] = r2;
                bh[2*p+1][0] = r1; bh[2*p+1][1] = r3;
                ldm_x4(r0, r1, r2, r3, ad + 8192);
                bl[2*p][0] = r0; bl[2*p][1] = r2;
                bl[2*p+1][0] = r1; bl[2*p+1][1] = r3;
            }
#pragma unroll
            for (int mf = 0; mf < 2; mf++)
#pragma unroll
                for (int n = 0; n < 8; n++) {
                    mma_bf16(acc[mf][n], ah[mf], bh[n]);
                    mma_bf16(acc[mf][n], ah[mf], bl[n]);
                    mma_bf16(acc[mf][n], al[mf], bh[n]);
                }
        }
        __syncthreads();
    }

#pragma unroll
    for (int mf = 0; mf < 2; mf++) {
        int r1 = bm + wm * 32 + mf * 16 + (lane >> 2);
#pragma unroll
        for (int n = 0; n < 8; n++) {
            int col = bn + wn * 64 + n * 8 + (lane & 3) * 2;
            float b0 = bias[col], b1 = bias[col + 1];
            float v00 = acc[mf][n][0] + b0, v01 = acc[mf][n][1] + b1;
            float v10 = acc[mf][n][2] + b0, v11 = acc[mf][n][3] + b1;
            if (SPLIT_OUT) {
                __nv_bfloat16 l0, l1;
                __nv_bfloat162 h = pack_split_hi(v00, v01, l0, l1);
                *reinterpret_cast<__nv_bfloat162*>(&Chi[(long long)r1 * N + col]) = h;
                *reinterpret_cast<__nv_bfloat162*>(&Clo[(long long)r1 * N + col]) =
                    __nv_bfloat162(l0, l1);
                h = pack_split_hi(v10, v11, l0, l1);
                *reinterpret_cast<__nv_bfloat162*>(&Chi[(long long)(r1 + 8) * N + col]) = h;
                *reinterpret_cast<__nv_bfloat162*>(&Clo[(long long)(r1 + 8) * N + col]) =
                    __nv_bfloat162(l0, l1);
            } else {
                *reinterpret_cast<float2*>(&C[(long long)r1 * N + col]) =
                    make_float2(v00, v01);
                *reinterpret_cast<float2*>(&C[(long long)(r1 + 8) * N + col]) =
                    make_float2(v10, v11);
            }
        }
    }
}

// ---------------------------------------------------------------------------
// Persistent fused attention: one CTA per (b,h); K/V resident in smem,
// loop over 16 t-tiles of 64 rows. Outputs split bf16 Y.
// smem layout (bytes):
//  Khi@0 Klo@32768 Vhi@65536 Vlo@98304 (each 32 KB)
//  Qhi@131072 Qlo@139264 (each 8 KB)
//  Phi@147456 Plo@180224 (each 32 KB)
//  redmax@212992 redsum@214016
// ---------------------------------------------------------------------------
#define FA_KH   0
#define FA_KL   32768
#define FA_VH   65536
#define FA_VL   98304
#define FA_QH   131072
#define FA_QL   139264
#define FA_PH   147456
#define FA_PL   180224
#define FA_REDM 212992
#define FA_REDS 214016
#define FA_SMEM 215040

__global__ void __launch_bounds__(256)
fa_kernel(const __nv_bfloat16* __restrict__ Qh, const __nv_bfloat16* __restrict__ Ql,
          const __nv_bfloat16* __restrict__ KVh, const __nv_bfloat16* __restrict__ KVl,
          __nv_bfloat16* __restrict__ Yh, __nv_bfloat16* __restrict__ Yl)
{
    extern __shared__ char smem[];
    const uint32_t sb = smem_u32(smem);
    const int tid  = threadIdx.x;
    const int lane = tid & 31;
    const int warp = tid >> 5;
    const int bh = blockIdx.x;
    const int b = bh >> 4, h = bh & 15;

    const int rq = lane >> 2, cq = lane & 3;
    const int wm = warp >> 2;   // 0..1
    const int wn = warp & 3;    // 0..3

    float* red_max = reinterpret_cast<float*>(smem + FA_REDM);
    float* red_sum = reinterpret_cast<float*>(smem + FA_REDS);

    // ---- load K and V (hi/lo) once ----
    {
        const long long kbase = ((long long)(b * 256)) * 2048 + h * 64;
#pragma unroll
        for (int i = tid; i < 2048; i += 256) {
            int row = i >> 3, c = i & 7;
            uint32_t sw = (uint32_t)((c ^ (row & 7)) << 4);
            long long go = (long long)row * 2048 + c * 8;
            cp16(sb + FA_KH + row * 128 + sw, KVh + kbase + go);
            cp16(sb + FA_KL + row * 128 + sw, KVl + kbase + go);
            cp16(sb + FA_VH + row * 128 + sw, KVh + kbase + 1024 + go);
            cp16(sb + FA_VL + row * 128 + sw, KVl + kbase + 1024 + go);
        }
        cp_commit();
        asm volatile("cp.async.wait_group 0;" ::: "memory");
        __syncthreads();
    }

    for (int tt = 0; tt < 16; tt++) {
        const int t0 = tt * 64;
        const bool need_mask = (t0 < Slen);
        const int tmax = t0 + 63;

        // ---- load Q tile ----
        {
            const long long qbase = ((long long)(b * 1024 + t0)) * 1024 + h * 64;
#pragma unroll
            for (int i = tid; i < 512; i += 256) {
                int row = i >> 3, c = i & 7;
                uint32_t sw = (uint32_t)((c ^ (row & 7)) << 4);
                cp16(sb + FA_QH + row * 128 + sw, Qh + qbase + (long long)row * 1024 + c * 8);
                cp16(sb + FA_QL + row * 128 + sw, Ql + qbase + (long long)row * 1024 + c * 8);
            }
            cp_commit();
            asm volatile("cp.async.wait_group 0;" ::: "memory");
            __syncthreads();
        }

        // ---- phase 1: S = Q K^T (64x256x64) ----
        float acc[2][8][4];
#pragma unroll
        for (int m = 0; m < 2; m++)
#pragma unroll
            for (int n = 0; n < 8; n++)
#pragma unroll
                for (int j = 0; j < 4; j++) acc[m][n][j] = 0.0f;

#pragma unroll
        for (int ks = 0; ks < 4; ks++) {
            uint32_t ah[2][4], al[2][4];
#pragma unroll
            for (int mf = 0; mf < 2; mf++) {
                int row = wm * 32 + mf * 16 + (lane & 15);
                int ch  = ks * 2 + (lane >> 4);
                uint32_t ad = sb + FA_QH + row * 128 + (uint32_t)((ch ^ (row & 7)) << 4);
                ldm_x4(ah[mf][0], ah[mf][1], ah[mf][2], ah[mf][3], ad);
                ldm_x4(al[mf][0], al[mf][1], al[mf][2], al[mf][3], ad + 8192);
            }
            uint32_t bh_[8][2], bl_[8][2];
#pragma unroll
            for (int p = 0; p < 4; p++) {
                if (need_mask && (wn * 64 + p * 16) > tmax) continue;
                int row = wn * 64 + p * 16 + (lane & 15);
                int ch  = ks * 2 + (lane >> 4);
                uint32_t ad = sb + FA_KH + row * 128 + (uint32_t)((ch ^ (row & 7)) << 4);
                uint32_t r0, r1, r2, r3;
                ldm_x4(r0, r1, r2, r3, ad);
                bh_[2*p][0] = r0; bh_[2*p][1] = r2;
                bh_[2*p+1][0] = r1; bh_[2*p+1][1] = r3;
                ldm_x4(r0, r1, r2, r3, ad + 32768);
                bl_[2*p][0] = r0; bl_[2*p][1] = r2;
                bl_[2*p+1][0] = r1; bl_[2*p+1][1] = r3;
            }
#pragma unroll
            for (int mf = 0; mf < 2; mf++)
#pragma unroll
                for (int n = 0; n < 8; n++) {
                    if (need_mask && (wn * 64 + n * 8) > tmax) continue;
                    mma_bf16(acc[mf][n], ah[mf], bh_[n]);
                    mma_bf16(acc[mf][n], ah[mf], bl_[n]);
                    mma_bf16(acc[mf][n], al[mf], bh_[n]);
                }
        }

        // ---- softmax ----
#pragma unroll
        for (int mf = 0; mf < 2; mf++)
#pragma unroll
            for (int sub = 0; sub < 2; sub++) {
                int rl = wm * 32 + mf * 16 + sub * 8 + rq;
                int trow = t0 + rl;
                float m = -1e30f;
#pragma unroll
                for (int nf = 0; nf < 8; nf++) {
                    int col = wn * 64 + nf * 8 + cq * 2;
                    float v0 = acc[mf][nf][sub*2]     * 0.125f;
                    float v1 = acc[mf][nf][sub*2 + 1] * 0.125f;
                    if (need_mask) {
                        if (col     > trow) v0 = -1e30f;
                        if (col + 1 > trow) v1 = -1e30f;
                    }
                    acc[mf][nf][sub*2]     = v0;
                    acc[mf][nf][sub*2 + 1] = v1;
                    m = fmaxf(m, fmaxf(v0, v1));
                }
                m = fmaxf(m, __shfl_xor_sync(0xffffffffu, m, 1));
                m = fmaxf(m, __shfl_xor_sync(0xffffffffu, m, 2));
                if (cq == 0) red_max[wn * 64 + rl] = m;
            }
        __syncthreads();

#pragma unroll
        for (int mf = 0; mf < 2; mf++)
#pragma unroll
            for (int sub = 0; sub < 2; sub++) {
                int rl = wm * 32 + mf * 16 + sub * 8 + rq;
                float M = fmaxf(fmaxf(red_max[rl], red_max[64 + rl]),
                                fmaxf(red_max[128 + rl], red_max[192 + rl]));
                float s = 0.0f;
#pragma unroll
                for (int nf = 0; nf < 8; nf++) {
                    float e0 = __expf(acc[mf][nf][sub*2]     - M);
                    float e1 = __expf(acc[mf][nf][sub*2 + 1] - M);
                    acc[mf][nf][sub*2]     = e0;
                    acc[mf][nf][sub*2 + 1] = e1;
                    s += e0 + e1;
                }
                s += __shfl_xor_sync(0xffffffffu, s, 1);
                s += __shfl_xor_sync(0xffffffffu, s, 2);
                if (cq == 0) red_sum[wn * 64 + rl] = s;
            }
        __syncthreads();

        // ---- store P (unnormalized) split bf16 ----
#pragma unroll
        for (int mf = 0; mf < 2; mf++)
#pragma unroll
            for (int sub = 0; sub < 2; sub++) {
                int rl = wm * 32 + mf * 16 + sub * 8 + rq;
#pragma unroll
                for (int nf = 0; nf < 8; nf++) {
                    int col = wn * 64 + nf * 8 + cq * 2;
                    __nv_bfloat16 l0, l1;
                    __nv_bfloat162 hh = pack_split_hi(acc[mf][nf][sub*2],
                                                      acc[mf][nf][sub*2 + 1], l0, l1);
                    int chnk = col >> 3;
                    uint32_t off = (uint32_t)(rl * 512 + ((chnk ^ (rl & 7)) << 4) + (col & 7) * 2);
                    *reinterpret_cast<__nv_bfloat162*>(smem + FA_PH + off) = hh;
                    *reinterpret_cast<__nv_bfloat162*>(smem + FA_PL + off) =
                        __nv_bfloat162(l0, l1);
                }
            }
        __syncthreads();

        // ---- phase 2: Y = P V ----
        const int nks = need_mask ? ((tmax >> 4) + 1) : 16;
        float acc2[2][2][4];
#pragma unroll
        for (int m = 0; m < 2; m++)
#pragma unroll
            for (int n = 0; n < 2; n++)
#pragma unroll
                for (int j = 0; j < 4; j++) acc2[m][n][j] = 0.0f;

        for (int ks = 0; ks < nks; ks++) {
            uint32_t ph[2][4], pl[2][4];
#pragma unroll
            for (int mf = 0; mf < 2; mf++) {
                int row = wm * 32 + mf * 16 + (lane & 15);
                int ch  = ks * 2 + (lane >> 4);
                uint32_t ad = sb + FA_PH + row * 512 + (uint32_t)((ch ^ (row & 7)) << 4);
                ldm_x4(ph[mf][0], ph[mf][1], ph[mf][2], ph[mf][3], ad);
                ldm_x4(pl[mf][0], pl[mf][1], pl[mf][2], pl[mf][3], ad + 32768);
            }
            uint32_t vh_[2][2], vl_[2][2];
            {
                int g = lane >> 3;
                int srow = ks * 16 + (g & 1) * 8 + (lane & 7);
                int dch  = wn * 2 + (g >> 1);
                uint32_t ad = sb + FA_VH + srow * 128 + (uint32_t)((dch ^ (srow & 7)) << 4);
                uint32_t r0, r1, r2, r3;
                ldm_x4t(r0, r1, r2, r3, ad);
                vh_[0][0] = r0; vh_[0][1] = r1; vh_[1][0] = r2; vh_[1][1] = r3;
                ldm_x4t(r0, r1, r2, r3, ad + 32768);
                vl_[0][0] = r0; vl_[0][1] = r1; vl_[1][0] = r2; vl_[1][1] = r3;
            }
#pragma unroll
            for (int mf = 0; mf < 2; mf++)
#pragma unroll
                for (int nf = 0; nf < 2; nf++) {
                    mma_bf16(acc2[mf][nf], ph[mf], vh_[nf]);
                    mma_bf16(acc2[mf][nf], ph[mf], vl_[nf]);
                    mma_bf16(acc2[mf][nf], pl[mf], vh_[nf]);
                }
        }

        // ---- epilogue: normalize, split-bf16 store ----
#pragma unroll
        for (int mf = 0; mf < 2; mf++)
#pragma unroll
            for (int sub = 0; sub < 2; sub++) {
                int rl = wm * 32 + mf * 16 + sub * 8 + rq;
                float inv = 1.0f / (red_sum[rl] + red_sum[64 + rl] +
                                    red_sum[128 + rl] + red_sum[192 + rl]);
                long long yo = ((long long)(b * 1024 + t0 + rl)) * 1024 + h * 64;
#pragma unroll
                for (int nf = 0; nf < 2; nf++) {
                    int col = wn * 16 + nf * 8 + cq * 2;
                    float v0 = acc2[mf][nf][sub*2]     * inv;
                    float v1 = acc2[mf][nf][sub*2 + 1] * inv;
                    __nv_bfloat16 l0, l1;
                    __nv_bfloat162 hh = pack_split_hi(v0, v1, l0, l1);
                    *reinterpret_cast<__nv_bfloat162*>(&Yh[yo + col]) = hh;
                    *reinterpret_cast<__nv_bfloat162*>(&Yl[yo + col]) = __nv_bfloat162(l0, l1);
                }
            }
        __syncthreads();   // P / red buffers reused next iteration
    }
}

// ---------------------------------------------------------------------------
// Launch
// ---------------------------------------------------------------------------
extern "C" void kernel_launch(void* const* d_in, const int* in_sizes, int n_in,
                              void* d_out, int out_size)
{
    const float* x  = (const float*)d_in[0];
    const float* ft = (const float*)d_in[1];
    const float* Wq = (const float*)d_in[2];
    const float* bq = (const float*)d_in[3];
    const float* Aq = (const float*)d_in[4];
    const float* Bq = (const float*)d_in[5];
    const float* Wf = (const float*)d_in[6];
    const float* bfv= (const float*)d_in[7];
    const float* Af = (const float*)d_in[8];
    const float* Bf = (const float*)d_in[9];
    const float* Wp = (const float*)d_in[10];
    const float* bp = (const float*)d_in[11];
    const float* Ap = (const float*)d_in[12];
    const float* Bp = (const float*)d_in[13];
    float* out = (float*)d_out;

    __nv_bfloat16 *xhi, *xlo, *fhi, *flo, *yhi, *ylo;
    __nv_bfloat16 *wqhi, *wqlo, *wfhi, *wflo, *wphi, *wplo;
    __nv_bfloat16 *qh, *ql, *kvh, *kvl;
    __nv_bfloat16 *tqh, *tql, *tfh, *tfl, *tph, *tpl;
    __nv_bfloat16 *bqh, *bql, *bfh, *bfl, *bph, *bpl;
    cudaGetSymbolAddress((void**)&xhi, g_xhi);  cudaGetSymbolAddress((void**)&xlo, g_xlo);
    cudaGetSymbolAddress((void**)&fhi, g_fhi);  cudaGetSymbolAddress((void**)&flo, g_flo);
    cudaGetSymbolAddress((void**)&yhi, g_yhi);  cudaGetSymbolAddress((void**)&ylo, g_ylo);
    cudaGetSymbolAddress((void**)&wqhi, g_wqhi); cudaGetSymbolAddress((void**)&wqlo, g_wqlo);
    cudaGetSymbolAddress((void**)&wfhi, g_wfhi); cudaGetSymbolAddress((void**)&wflo, g_wflo);
    cudaGetSymbolAddress((void**)&wphi, g_wphi); cudaGetSymbolAddress((void**)&wplo, g_wplo);
    cudaGetSymbolAddress((void**)&qh, g_qh);    cudaGetSymbolAddress((void**)&ql, g_ql);
    cudaGetSymbolAddress((void**)&kvh, g_kvh);  cudaGetSymbolAddress((void**)&kvl, g_kvl);
    cudaGetSymbolAddress((void**)&tqh, g_tqh);  cudaGetSymbolAddress((void**)&tql, g_tql);
    cudaGetSymbolAddress((void**)&tfh, g_tfh);  cudaGetSymbolAddress((void**)&tfl, g_tfl);
    cudaGetSymbolAddress((void**)&tph, g_tph);  cudaGetSymbolAddress((void**)&tpl, g_tpl);
    cudaGetSymbolAddress((void**)&bqh, g_bqh);  cudaGetSymbolAddress((void**)&bql, g_bql);
    cudaGetSymbolAddress((void**)&bfh, g_bfh);  cudaGetSymbolAddress((void**)&bfl, g_bfl);
    cudaGetSymbolAddress((void**)&bph, g_bph);  cudaGetSymbolAddress((void**)&bpl, g_bpl);

    cudaFuncSetAttribute(mma_gemm<false>, cudaFuncAttributeMaxDynamicSharedMemorySize, MG_SMEM);
    cudaFuncSetAttribute(mma_gemm<true>,  cudaFuncAttributeMaxDynamicSharedMemorySize, MG_SMEM);
    cudaFuncSetAttribute(fa_kernel, cudaFuncAttributeMaxDynamicSharedMemorySize, FA_SMEM);

    const float SC = 1.0f / 16.0f;

    split_multi<<<(SEG4 + 255)/256, 256>>>(
        (const float4*)x, (const float4*)Wq, (const float4*)ft,
        (const float4*)Wf, (const float4*)Wp,
        (__nv_bfloat162*)xhi,  (__nv_bfloat162*)xlo,
        (__nv_bfloat162*)wqhi, (__nv_bfloat162*)wqlo,
        (__nv_bfloat162*)fhi,  (__nv_bfloat162*)flo,
        (__nv_bfloat162*)wfhi, (__nv_bfloat162*)wflo,
        (__nv_bfloat162*)wphi, (__nv_bfloat162*)wplo);

    lora_t_merged<<<160, 256>>>(x, Aq, ft, Af, tqh, tql, tfh, tfl, SC);
    splitpad_multi<<<128, 256>>>(Bq, Bf, Bp, bqh, bql, bfh, bfl, bph, bpl);

    // Q projection -> split bf16
    mma_gemm<true><<<dim3(8, 64), 256, MG_SMEM>>>(xhi, xlo, wqhi, wqlo,
        tqh, tql, bqh, bql, nullptr, qh, ql, 1024, 1024, bq);

    // KV projection -> split bf16
    mma_gemm<true><<<dim3(16, 16), 256, MG_SMEM>>>(fhi, flo, wfhi, wflo,
        tfh, tfl, bfh, bfl, nullptr, kvh, kvl, 1024, 2048, bfv);

    // persistent fused attention -> split bf16 Y
    fa_kernel<<<128, 256, FA_SMEM>>>(qh, ql, kvh, kvl, yhi, ylo);

    // LoRA for P from split Y
    lora_t_split<<<128, 256>>>(yhi, ylo, Ap, tph, tpl, SC);

    // out = y @ Wp^T + bp + lora  (fp32 out)
    mma_gemm<false><<<dim3(8, 64), 256, MG_SMEM>>>(yhi, ylo, wphi, wplo,
        tph, tpl, bph, bpl, out, nullptr, nullptr, 1024, 1024, bp);
}